// round 12
// baseline (speedup 1.0000x reference)
#include <cuda_runtime.h>
#include <math.h>

#define NB 4
#define FH 480
#define FW 640
#define NPIX (FH*FW)
#define NSEM 16
#define C_OBS 20
#define VR 100
#define HZ 80
#define MC 480
#define NCELL (VR*VR)          // 10000
#define G0_PER_B (NCELL*HZ)    // 800000
#define AG_Z0 13
#define AG_NZ 12
#define GS_PER_B (NCELL*AG_NZ) // 120000
#define WIN 160

#define SPLAT_BLOCKS (NB*NPIX/256)                 // 4800
#define STREAM_N4    ((size_t)NB*C_OBS*MC*MC/4)    // 4,608,000 float4
#define STREAM_BLOCKS ((int)(STREAM_N4/256))       // 18000
#define ZERO_BLOCKS  ((NB*GS_PER_B*16/4 + 255)/256) // 7500
#define A_BLOCKS     (ZERO_BLOCKS + STREAM_BLOCKS)  // 25500

// Output layout: fp_map_pred (NB*NCELL) | map_pred (NB*20*480*480) | poses (12) | poses (12)
#define OUT_MAP_OFF ((size_t)NB*NCELL)
#define OUT_POSE_OFF (OUT_MAP_OFF + (size_t)NB*C_OBS*MC*MC)

// ---------- scratch ----------
__device__ __align__(16) float g_g0a[NB*G0_PER_B];   // ch-0, even-parity pairs; slot z = voxel z
__device__ __align__(16) float g_g0b[NB*G0_PER_B];   // ch-0, odd-parity pairs;  slot z = voxel z+1
__device__ __align__(16) float g_gs[NB*GS_PER_B*16]; // sem voxels [b][(x*100+y)*12+(z-13)][16]
__device__ __align__(16) float g_pall[NB*NCELL*20];  // interleaved proj: [b][y*100+x][20]
__device__ float g_params[NB*8];
__device__ float g_fcal;

// ---------- kernel A: zero scratch + pose + map stream (all independent, DRAM-bound) ----------
__global__ void __launch_bounds__(256) prep_kernel(const float* __restrict__ pose_obs,
                                                   const float* __restrict__ poses_last,
                                                   const float* __restrict__ maps_last,
                                                   float* __restrict__ dout) {
    if (blockIdx.x < ZERO_BLOCKS) {
        int t = blockIdx.x*256 + threadIdx.x;
        if (t == 0) {
            g_fcal = (float)(320.0 / tan(39.5 * 3.14159265358979323846 / 180.0));
        }
        if (blockIdx.x == 0 && threadIdx.x < NB) {
            int b = threadIdx.x;
            const float DEGf = (float)57.29577951308232;
            float pl0 = poses_last[b*3+0], pl1 = poses_last[b*3+1], pl2 = poses_last[b*3+2];
            float po0 = pose_obs[b*3+0],  po1 = pose_obs[b*3+1],  po2 = pose_obs[b*3+2];
            float t0 = pl2 / DEGf;
            float s0 = sinf(t0), c0 = cosf(t0);
            float y_new = pl1 + po0*s0 + po1*c0;
            float x_new = pl0 + po0*c0 - po1*s0;
            float t_new = pl2 + po2*DEGf;
            t_new = fmodf(t_new - 180.0f, 360.0f) + 180.0f;
            t_new = fmodf(t_new + 180.0f, 360.0f) - 180.0f;

            dout[OUT_POSE_OFF      + b*3+0] = x_new;
            dout[OUT_POSE_OFF      + b*3+1] = y_new;
            dout[OUT_POSE_OFF      + b*3+2] = t_new;
            dout[OUT_POSE_OFF + 12 + b*3+0] = x_new;
            dout[OUT_POSE_OFF + 12 + b*3+1] = y_new;
            dout[OUT_POSE_OFF + 12 + b*3+2] = t_new;

            float stx = -(x_new*100.0f/5.0f - 240.0f)/240.0f;
            float sty = -(y_new*100.0f/5.0f - 240.0f)/240.0f;
            float stt = (90.0f - t_new) * (float)0.017453292519943295;
            float ct = cosf(stt), st = sinf(stt);
            float dx = stx * 239.5f;
            float dy = sty * 239.5f;
            g_params[b*8+0] = ct;
            g_params[b*8+1] = st;
            g_params[b*8+2] = dx;
            g_params[b*8+3] = dy;

            float u0 = 189.0f/239.5f - 1.0f, u1 = 290.0f/239.5f - 1.0f;
            float v0 = 239.0f/239.5f - 1.0f, v1 = 340.0f/239.5f - 1.0f;
            float gxmin = 1e9f, gxmax = -1e9f, gymin = 1e9f, gymax = -1e9f;
            #pragma unroll
            for (int k = 0; k < 4; k++) {
                float u = (k & 1) ? u1 : u0;
                float v = (k & 2) ? v1 : v0;
                float gx = ct*u + st*v;
                float gy = -st*u + ct*v;
                gxmin = fminf(gxmin, gx); gxmax = fmaxf(gxmax, gx);
                gymin = fminf(gymin, gy); gymax = fmaxf(gymax, gy);
            }
            float txmin = (gxmin + 1.0f)*239.5f, txmax = (gxmax + 1.0f)*239.5f;
            float tymin = (gymin + 1.0f)*239.5f, tymax = (gymax + 1.0f)*239.5f;
            g_params[b*8+4] = floorf(tymin - dy - 3.0f);
            g_params[b*8+5] = ceilf (tymax - dy + 3.0f);
            g_params[b*8+6] = floorf(txmin - dx - 3.0f);
            g_params[b*8+7] = ceilf (txmax - dx + 3.0f);
        }
        float4 z = make_float4(0.f,0.f,0.f,0.f);
        const int n0 = NB*G0_PER_B/4;       // 800000
        const int n1 = NB*GS_PER_B*16/4;    // 1920000
        if (t < n0) ((float4*)g_g0a)[t] = z;
        if (t < n0) ((float4*)g_g0b)[t] = z;
        if (t < n1) ((float4*)g_gs)[t] = z;
    } else {
        size_t t = (size_t)(blockIdx.x - ZERO_BLOCKS)*256 + threadIdx.x;
        float4 v = ((const float4*)maps_last)[t];
        v.x = fmaxf(v.x, 0.0f); v.y = fmaxf(v.y, 0.0f);
        v.z = fmaxf(v.z, 0.0f); v.w = fmaxf(v.w, 0.0f);
        ((float4*)(dout + OUT_MAP_OFF))[t] = v;
    }
}

// ---------- trilinear splat (pure, no stream partner) ----------
__global__ void __launch_bounds__(256) splat_kernel(const float* __restrict__ obs,
                                                    const float* __restrict__ sh) {
    int t = blockIdx.x*blockDim.x + threadIdx.x;
    int b   = t / NPIX;
    int pix = t - b*NPIX;
    int i   = pix / FW;
    int j   = pix - i*FW;

    const float* obs_b = obs + (size_t)b*C_OBS*NPIX;
    float depth = __ldg(&obs_b[3*NPIX + pix]);
    float4 s4   = __ldg(&((const float4*)sh)[(size_t)b*NPIX + pix]);

    float fc = g_fcal;
    float X = ((float)j - 319.5f) * depth / fc;
    float Z = (239.5f - (float)i) * depth / fc;

    float xn = ((X + 250.0f)/5.0f - 50.0f)/100.0f*2.0f;
    float yn = (depth/5.0f - 50.0f)/100.0f*2.0f;
    float zn = ((Z + 88.0f)/5.0f - 32.0f)/80.0f*2.0f;
    xn = fminf(fmaxf(xn, -1.0f), 1.0f);
    yn = fminf(fmaxf(yn, -1.0f), 1.0f);
    zn = fminf(fmaxf(zn, -1.0f), 1.0f);

    float posx = xn*50.0f + 50.0f;
    float posy = yn*50.0f + 50.0f;
    float posz = zn*40.0f + 40.0f;

    float fx = floorf(posx), fy = floorf(posy), fz = floorf(posz);
    float wx[2], wy[2], wz[2];
    int   px_[2], py_[2], pz_[2];
    #pragma unroll
    for (int k = 0; k < 2; k++) {
        float p;
        p = fx + (float)k; { bool s = (p > 0.0f && p < 100.0f); wx[k] = s ? (1.0f - fabsf(posx - p)) : 0.0f; px_[k] = (int)p; }
        p = fy + (float)k; { bool s = (p > 0.0f && p < 100.0f); wy[k] = s ? (1.0f - fabsf(posy - p)) : 0.0f; py_[k] = (int)p; }
        p = fz + (float)k; { bool s = (p > 0.0f && p <  80.0f); wz[k] = s ? (1.0f - fabsf(posz - p)) : 0.0f; pz_[k] = (int)p; }
    }
    if ((wx[0]==0.0f && wx[1]==0.0f) || (wy[0]==0.0f && wy[1]==0.0f) || (wz[0]==0.0f && wz[1]==0.0f))
        return;

    float sfac = 1.0f + (s4.x + s4.y + s4.z + s4.w) * 0.25f;

    int pz0 = pz_[0], pz1 = pz_[1];
    float wz0 = sfac*wz[0], wz1 = sfac*wz[1];
    bool band0 = (wz[0] != 0.0f) && (pz0 >= AG_Z0) && (pz0 < AG_Z0 + AG_NZ);
    bool band1 = (wz[1] != 0.0f) && (pz1 >= AG_Z0) && (pz1 < AG_Z0 + AG_NZ);

    int odd = pz0 & 1;
    float* g0base = (odd ? g_g0b : g_g0a) + (size_t)b*G0_PER_B + (pz0 - odd);

    float semv[16];
    if (band0 | band1) {
        #pragma unroll
        for (int c = 0; c < 16; c++)
            semv[c] = __ldg(&obs_b[(4+c)*NPIX + pix]) * sfac;
    }

    float* gsb = g_gs + (size_t)b*GS_PER_B*16;

    #pragma unroll
    for (int kx = 0; kx < 2; kx++) {
        #pragma unroll
        for (int ky = 0; ky < 2; ky++) {
            float wxy = wx[kx]*wy[ky];
            if (wxy == 0.0f) continue;
            int cellxy = px_[kx]*100 + py_[ky];

            atomicAdd((float2*)(g0base + cellxy*80), make_float2(wxy*wz0, wxy*wz1));

            if (band0) {
                float w = wxy*wz[0];
                float* dst = gsb + ((size_t)cellxy*AG_NZ + (pz0 - AG_Z0))*16;
                atomicAdd((float4*)(dst+ 0), make_float4(semv[ 0]*w, semv[ 1]*w, semv[ 2]*w, semv[ 3]*w));
                atomicAdd((float4*)(dst+ 4), make_float4(semv[ 4]*w, semv[ 5]*w, semv[ 6]*w, semv[ 7]*w));
                atomicAdd((float4*)(dst+ 8), make_float4(semv[ 8]*w, semv[ 9]*w, semv[10]*w, semv[11]*w));
                atomicAdd((float4*)(dst+12), make_float4(semv[12]*w, semv[13]*w, semv[14]*w, semv[15]*w));
            }
            if (band1) {
                float w = wxy*wz[1];
                float* dst = gsb + ((size_t)cellxy*AG_NZ + (pz1 - AG_Z0))*16;
                atomicAdd((float4*)(dst+ 0), make_float4(semv[ 0]*w, semv[ 1]*w, semv[ 2]*w, semv[ 3]*w));
                atomicAdd((float4*)(dst+ 4), make_float4(semv[ 4]*w, semv[ 5]*w, semv[ 6]*w, semv[ 7]*w));
                atomicAdd((float4*)(dst+ 8), make_float4(semv[ 8]*w, semv[ 9]*w, semv[10]*w, semv[11]*w));
                atomicAdd((float4*)(dst+12), make_float4(semv[12]*w, semv[13]*w, semv[14]*w, semv[15]*w));
            }
        }
    }
}

// ---------- proj : g0-half and sem-half thread groups (R9 measured-good) ----------
__global__ void __launch_bounds__(256) proj_kernel(float* __restrict__ dout) {
    const int N4 = NB*NCELL*4;
    int t = blockIdx.x*blockDim.x + threadIdx.x;

    if (t < N4) {
        int q = t & 3;
        int cellIdx = t >> 2;
        int b   = cellIdx / NCELL;
        int cxy = cellIdx - b*NCELL;
        int x = cxy / 100, y = cxy - x*100;
        int cell = y*100 + x;

        const float* acell = g_g0a + (size_t)b*G0_PER_B + (size_t)cxy*80;
        const float* bcell = g_g0b + (size_t)b*G0_PER_B + (size_t)cxy*80;
        const float4* a4p = (const float4*)acell + q*5;
        const float4* b4p = (const float4*)bcell + q*5;

        float prev = (q == 0) ? 0.0f : bcell[q*20 - 1];

        float a_all = 0.0f, a_ag = 0.0f;
        #pragma unroll
        for (int k = 0; k < 5; k++) {
            float4 a4 = a4p[k];
            float4 b4 = b4p[k];
            int z = q*20 + k*4;
            float v0 = rintf(a4.x + prev);
            float v1 = rintf(a4.y + b4.x);
            float v2 = rintf(a4.z + b4.y);
            float v3 = rintf(a4.w + b4.z);
            prev = b4.w;
            a_all += v0 + v1 + v2 + v3;
            a_ag += (z+0 >= 13 && z+0 < 25) ? v0 : 0.0f;
            a_ag += (z+1 >= 13 && z+1 < 25) ? v1 : 0.0f;
            a_ag += (z+2 >= 13 && z+2 < 25) ? v2 : 0.0f;
            a_ag += (z+3 >= 13 && z+3 < 25) ? v3 : 0.0f;
        }

        a_all += __shfl_xor_sync(0xFFFFFFFFu, a_all, 1);
        a_all += __shfl_xor_sync(0xFFFFFFFFu, a_all, 2);
        a_ag  += __shfl_xor_sync(0xFFFFFFFFu, a_ag, 1);
        a_ag  += __shfl_xor_sync(0xFFFFFFFFu, a_ag, 2);

        if (q == 0) {
            float pm = fminf(fmaxf(a_ag, 0.0f), 1.0f);
            float pe = fminf(fmaxf(a_all, 0.0f), 1.0f);
            float* rec = g_pall + ((size_t)b*NCELL + cell)*20;
            rec[0] = pm;
            rec[1] = pe;
            dout[(size_t)b*NCELL + cell] = pm;
        }
    } else {
        int u = t - N4;
        if (u >= N4) return;
        int q = u & 3;
        int cellIdx = u >> 2;
        int b   = cellIdx / NCELL;
        int cxy = cellIdx - b*NCELL;
        int x = cxy / 100, y = cxy - x*100;
        int cell = y*100 + x;

        const float4* gsp = (const float4*)(g_gs + ((size_t)b*GS_PER_B + (size_t)cxy*AG_NZ)*16) + q;
        float4 acc = make_float4(0.f,0.f,0.f,0.f);
        #pragma unroll
        for (int zz = 0; zz < AG_NZ; zz++) {
            float4 v = gsp[zz*4];
            acc.x += rintf(v.x);
            acc.y += rintf(v.y);
            acc.z += rintf(v.z);
            acc.w += rintf(v.w);
        }

        float* rec = g_pall + ((size_t)b*NCELL + cell)*20;
        rec[2 + q*4 + 0] = fminf(fmaxf(acc.x / 5.0f, 0.0f), 1.0f);
        rec[2 + q*4 + 1] = fminf(fmaxf(acc.y / 5.0f, 0.0f), 1.0f);
        rec[2 + q*4 + 2] = fminf(fmaxf(acc.z / 5.0f, 0.0f), 1.0f);
        rec[2 + q*4 + 3] = fminf(fmaxf(acc.w / 5.0f, 0.0f), 1.0f);
        if (q == 3) {
            rec[18] = 0.0f;
            rec[19] = 0.0f;
        }
    }
}

// ---------- window pass : 2 threads/pixel standalone (R10 measured 12.6us) ----------
__global__ void __launch_bounds__(256) map_window_kernel(const float* __restrict__ maps_last,
                                                         float* __restrict__ dout) {
    int t = blockIdx.x*blockDim.x + threadIdx.x;
    int half  = t & 1;
    int pixId = t >> 1;
    int b   = pixId / (WIN*WIN);
    int rem = pixId - b*(WIN*WIN);
    int li = rem / WIN, lj = rem - li*WIN;

    float ct = g_params[b*8+0], st = g_params[b*8+1];
    float dx = g_params[b*8+2], dy = g_params[b*8+3];
    int bi0 = (int)g_params[b*8+4], bi1 = (int)g_params[b*8+5];
    int bj0 = (int)g_params[b*8+6], bj1 = (int)g_params[b*8+7];

    int i = bi0 + li;
    int j = bj0 + lj;
    bool valid = (i <= bi1) && (j <= bj1) && (i >= 0) && (i < MC) && (j >= 0) && (j < MC);

    float xs = (float)j + dx, ys = (float)i + dy;
    float x0f = floorf(xs), y0f = floorf(ys);
    float wxb = xs - x0f, wxa = 1.0f - wxb;
    float wyb = ys - y0f, wya = 1.0f - wyb;
    int ix0 = (int)x0f, iy0 = (int)y0f;

    const float4* pall4 = (const float4*)(g_pall + (size_t)b*NCELL*20);

    float4 acc0 = make_float4(0,0,0,0), acc1 = acc0, acc2 = acc0, acc3 = acc0, acc4 = acc0;

    #pragma unroll
    for (int kk = 0; kk < 2; kk++) {
        int k  = half*2 + kk;
        int tx = ix0 + (k & 1);
        int ty = iy0 + (k >> 1);
        bool tvalid = valid && (tx >= 0) && (tx < MC) && (ty >= 0) && (ty < MC);
        float twk = ((k & 1) ? wxb : wxa) * ((k >> 1) ? wyb : wya);

        float gxr = -1.0f + (float)tx * (2.0f/479.0f);
        float gyr = -1.0f + (float)ty * (2.0f/479.0f);
        float xr = ((ct*gxr - st*gyr) + 1.0f) * 239.5f;
        float yr = ((st*gxr + ct*gyr) + 1.0f) * 239.5f;
        float rx0f = floorf(xr), ry0f = floorf(yr);
        float rb = xr - rx0f, ra = 1.0f - rb;
        float rd = yr - ry0f, rc = 1.0f - rd;
        int rx0 = (int)rx0f, ry0 = (int)ry0f;

        #pragma unroll
        for (int s = 0; s < 4; s++) {
            int ix = rx0 + (s & 1);
            int iy = ry0 + (s >> 1);
            bool in = tvalid && (ix >= 190) && (ix < 290) && (iy >= 240) && (iy < 340);
            if (in) {
                float rw = ((s & 1) ? rb : ra) * ((s >> 1) ? rd : rc);
                float w = twk * rw;
                const float4* rp = pall4 + ((iy - 240)*100 + (ix - 190))*5;
                float4 r0 = rp[0], r1 = rp[1], r2 = rp[2], r3 = rp[3], r4 = rp[4];
                acc0.x += w*r0.x; acc0.y += w*r0.y; acc0.z += w*r0.z; acc0.w += w*r0.w;
                acc1.x += w*r1.x; acc1.y += w*r1.y; acc1.z += w*r1.z; acc1.w += w*r1.w;
                acc2.x += w*r2.x; acc2.y += w*r2.y; acc2.z += w*r2.z; acc2.w += w*r2.w;
                acc3.x += w*r3.x; acc3.y += w*r3.y; acc3.z += w*r3.z; acc3.w += w*r3.w;
                acc4.x += w*r4.x; acc4.y += w*r4.y;
            }
        }
    }

    acc0.x += __shfl_xor_sync(0xFFFFFFFFu, acc0.x, 1);
    acc0.y += __shfl_xor_sync(0xFFFFFFFFu, acc0.y, 1);
    acc0.z += __shfl_xor_sync(0xFFFFFFFFu, acc0.z, 1);
    acc0.w += __shfl_xor_sync(0xFFFFFFFFu, acc0.w, 1);
    acc1.x += __shfl_xor_sync(0xFFFFFFFFu, acc1.x, 1);
    acc1.y += __shfl_xor_sync(0xFFFFFFFFu, acc1.y, 1);
    acc1.z += __shfl_xor_sync(0xFFFFFFFFu, acc1.z, 1);
    acc1.w += __shfl_xor_sync(0xFFFFFFFFu, acc1.w, 1);
    acc2.x += __shfl_xor_sync(0xFFFFFFFFu, acc2.x, 1);
    acc2.y += __shfl_xor_sync(0xFFFFFFFFu, acc2.y, 1);
    acc2.z += __shfl_xor_sync(0xFFFFFFFFu, acc2.z, 1);
    acc2.w += __shfl_xor_sync(0xFFFFFFFFu, acc2.w, 1);
    acc3.x += __shfl_xor_sync(0xFFFFFFFFu, acc3.x, 1);
    acc3.y += __shfl_xor_sync(0xFFFFFFFFu, acc3.y, 1);
    acc3.z += __shfl_xor_sync(0xFFFFFFFFu, acc3.z, 1);
    acc3.w += __shfl_xor_sync(0xFFFFFFFFu, acc3.w, 1);
    acc4.x += __shfl_xor_sync(0xFFFFFFFFu, acc4.x, 1);
    acc4.y += __shfl_xor_sync(0xFFFFFFFFu, acc4.y, 1);

    if (half != 0 || !valid) return;

    size_t base = (size_t)b*C_OBS*MC*MC + (size_t)i*MC + j;
    const float* mlp  = maps_last + base;
    float*       outp = dout + OUT_MAP_OFF + base;
    const size_t S = (size_t)MC*MC;

    outp[0]    = fmaxf(mlp[0],    acc0.x);
    outp[S]    = fmaxf(mlp[S],    acc0.y);
    outp[4*S]  = fmaxf(mlp[4*S],  acc0.z);
    outp[5*S]  = fmaxf(mlp[5*S],  acc0.w);
    outp[6*S]  = fmaxf(mlp[6*S],  acc1.x);
    outp[7*S]  = fmaxf(mlp[7*S],  acc1.y);
    outp[8*S]  = fmaxf(mlp[8*S],  acc1.z);
    outp[9*S]  = fmaxf(mlp[9*S],  acc1.w);
    outp[10*S] = fmaxf(mlp[10*S], acc2.x);
    outp[11*S] = fmaxf(mlp[11*S], acc2.y);
    outp[12*S] = fmaxf(mlp[12*S], acc2.z);
    outp[13*S] = fmaxf(mlp[13*S], acc2.w);
    outp[14*S] = fmaxf(mlp[14*S], acc3.x);
    outp[15*S] = fmaxf(mlp[15*S], acc3.y);
    outp[16*S] = fmaxf(mlp[16*S], acc3.z);
    outp[17*S] = fmaxf(mlp[17*S], acc3.w);
    outp[18*S] = fmaxf(mlp[18*S], acc4.x);
    outp[19*S] = fmaxf(mlp[19*S], acc4.y);
}

extern "C" void kernel_launch(void* const* d_in, const int* in_sizes, int n_in,
                              void* d_out, int out_size) {
    const float* obs        = (const float*)d_in[0];
    const float* pose_obs   = (const float*)d_in[1];
    const float* maps_last  = (const float*)d_in[2];
    const float* poses_last = (const float*)d_in[3];
    const float* sh         = (const float*)d_in[4];
    float* out = (float*)d_out;

    prep_kernel<<<A_BLOCKS, 256>>>(pose_obs, poses_last, maps_last, out);
    splat_kernel<<<SPLAT_BLOCKS, 256>>>(obs, sh);
    proj_kernel<<<(NB*NCELL*8 + 255)/256, 256>>>(out);
    map_window_kernel<<<NB*WIN*WIN*2/256, 256>>>(maps_last, out);
}

// round 13
// speedup vs baseline: 1.0805x; 1.0805x over previous
#include <cuda_runtime.h>
#include <math.h>

#define NB 4
#define FH 480
#define FW 640
#define NPIX (FH*FW)
#define NSEM 16
#define C_OBS 20
#define VR 100
#define HZ 80
#define MC 480
#define NCELL (VR*VR)          // 10000
#define G0_PER_B (NCELL*HZ)    // 800000
#define AG_Z0 13
#define AG_NZ 12
#define GS_PER_B (NCELL*AG_NZ) // 120000
#define WIN 160

#define SPLAT_BLOCKS (NB*NPIX/256)                 // 4800
#define STREAM_N4    ((size_t)NB*C_OBS*MC*MC/4)    // 4,608,000 float4
#define STREAM_BLOCKS ((int)(STREAM_N4/256))       // 18000
#define FAT_BLOCKS   (SPLAT_BLOCKS + STREAM_BLOCKS)

// Output layout: fp_map_pred (NB*NCELL) | map_pred (NB*20*480*480) | poses (12) | poses (12)
#define OUT_MAP_OFF ((size_t)NB*NCELL)
#define OUT_POSE_OFF (OUT_MAP_OFF + (size_t)NB*C_OBS*MC*MC)

// ---------- scratch ----------
__device__ __align__(16) float g_g0a[NB*G0_PER_B];   // ch-0, even-parity pairs; slot z = voxel z
__device__ __align__(16) float g_g0b[NB*G0_PER_B];   // ch-0, odd-parity pairs;  slot z = voxel z+1
__device__ __align__(16) float g_gs[NB*GS_PER_B*16]; // sem voxels [b][(x*100+y)*12+(z-13)][16]
__device__ __align__(16) float g_pall[NB*NCELL*20];  // interleaved proj: [b][y*100+x][20]
__device__ float g_params[NB*8];
__device__ float g_fcal;

// ---------- zero voxel scratch + pose update + sampling params (R8/R9 measured) ----------
__global__ void zero_pose_kernel(const float* __restrict__ pose_obs,
                                 const float* __restrict__ poses_last,
                                 float* __restrict__ dout) {
    int t = blockIdx.x*blockDim.x + threadIdx.x;
    if (t == 0) {
        g_fcal = (float)(320.0 / tan(39.5 * 3.14159265358979323846 / 180.0));
    }
    if (blockIdx.x == 0 && threadIdx.x < NB) {
        int b = threadIdx.x;
        const float DEGf = (float)57.29577951308232;
        float pl0 = poses_last[b*3+0], pl1 = poses_last[b*3+1], pl2 = poses_last[b*3+2];
        float po0 = pose_obs[b*3+0],  po1 = pose_obs[b*3+1],  po2 = pose_obs[b*3+2];
        float t0 = pl2 / DEGf;
        float s0 = sinf(t0), c0 = cosf(t0);
        float y_new = pl1 + po0*s0 + po1*c0;
        float x_new = pl0 + po0*c0 - po1*s0;
        float t_new = pl2 + po2*DEGf;
        t_new = fmodf(t_new - 180.0f, 360.0f) + 180.0f;
        t_new = fmodf(t_new + 180.0f, 360.0f) - 180.0f;

        dout[OUT_POSE_OFF      + b*3+0] = x_new;
        dout[OUT_POSE_OFF      + b*3+1] = y_new;
        dout[OUT_POSE_OFF      + b*3+2] = t_new;
        dout[OUT_POSE_OFF + 12 + b*3+0] = x_new;
        dout[OUT_POSE_OFF + 12 + b*3+1] = y_new;
        dout[OUT_POSE_OFF + 12 + b*3+2] = t_new;

        float stx = -(x_new*100.0f/5.0f - 240.0f)/240.0f;
        float sty = -(y_new*100.0f/5.0f - 240.0f)/240.0f;
        float stt = (90.0f - t_new) * (float)0.017453292519943295;
        float ct = cosf(stt), st = sinf(stt);
        float dx = stx * 239.5f;
        float dy = sty * 239.5f;
        g_params[b*8+0] = ct;
        g_params[b*8+1] = st;
        g_params[b*8+2] = dx;
        g_params[b*8+3] = dy;

        float u0 = 189.0f/239.5f - 1.0f, u1 = 290.0f/239.5f - 1.0f;
        float v0 = 239.0f/239.5f - 1.0f, v1 = 340.0f/239.5f - 1.0f;
        float gxmin = 1e9f, gxmax = -1e9f, gymin = 1e9f, gymax = -1e9f;
        #pragma unroll
        for (int k = 0; k < 4; k++) {
            float u = (k & 1) ? u1 : u0;
            float v = (k & 2) ? v1 : v0;
            float gx = ct*u + st*v;
            float gy = -st*u + ct*v;
            gxmin = fminf(gxmin, gx); gxmax = fmaxf(gxmax, gx);
            gymin = fminf(gymin, gy); gymax = fmaxf(gymax, gy);
        }
        float txmin = (gxmin + 1.0f)*239.5f, txmax = (gxmax + 1.0f)*239.5f;
        float tymin = (gymin + 1.0f)*239.5f, tymax = (gymax + 1.0f)*239.5f;
        g_params[b*8+4] = floorf(tymin - dy - 3.0f);
        g_params[b*8+5] = ceilf (tymax - dy + 3.0f);
        g_params[b*8+6] = floorf(txmin - dx - 3.0f);
        g_params[b*8+7] = ceilf (txmax - dx + 3.0f);
    }
    float4 z = make_float4(0.f,0.f,0.f,0.f);
    const int n0 = NB*G0_PER_B/4;       // 800000
    const int n1 = NB*GS_PER_B*16/4;    // 1920000
    if (t < n0) ((float4*)g_g0a)[t] = z;
    if (t < n0) ((float4*)g_g0b)[t] = z;
    if (t < n1) ((float4*)g_gs)[t] = z;
}

// ---------- splat body ----------
__device__ __forceinline__ void splat_body(int t, const float* __restrict__ obs,
                                           const float* __restrict__ sh) {
    int b   = t / NPIX;
    int pix = t - b*NPIX;
    int i   = pix / FW;
    int j   = pix - i*FW;

    const float* obs_b = obs + (size_t)b*C_OBS*NPIX;
    float depth = __ldg(&obs_b[3*NPIX + pix]);
    float4 s4   = __ldg(&((const float4*)sh)[(size_t)b*NPIX + pix]);

    float fc = g_fcal;
    float X = ((float)j - 319.5f) * depth / fc;
    float Z = (239.5f - (float)i) * depth / fc;

    float xn = ((X + 250.0f)/5.0f - 50.0f)/100.0f*2.0f;
    float yn = (depth/5.0f - 50.0f)/100.0f*2.0f;
    float zn = ((Z + 88.0f)/5.0f - 32.0f)/80.0f*2.0f;
    xn = fminf(fmaxf(xn, -1.0f), 1.0f);
    yn = fminf(fmaxf(yn, -1.0f), 1.0f);
    zn = fminf(fmaxf(zn, -1.0f), 1.0f);

    float posx = xn*50.0f + 50.0f;
    float posy = yn*50.0f + 50.0f;
    float posz = zn*40.0f + 40.0f;

    float fx = floorf(posx), fy = floorf(posy), fz = floorf(posz);
    float wx[2], wy[2], wz[2];
    int   px_[2], py_[2], pz_[2];
    #pragma unroll
    for (int k = 0; k < 2; k++) {
        float p;
        p = fx + (float)k; { bool s = (p > 0.0f && p < 100.0f); wx[k] = s ? (1.0f - fabsf(posx - p)) : 0.0f; px_[k] = (int)p; }
        p = fy + (float)k; { bool s = (p > 0.0f && p < 100.0f); wy[k] = s ? (1.0f - fabsf(posy - p)) : 0.0f; py_[k] = (int)p; }
        p = fz + (float)k; { bool s = (p > 0.0f && p <  80.0f); wz[k] = s ? (1.0f - fabsf(posz - p)) : 0.0f; pz_[k] = (int)p; }
    }
    if ((wx[0]==0.0f && wx[1]==0.0f) || (wy[0]==0.0f && wy[1]==0.0f) || (wz[0]==0.0f && wz[1]==0.0f))
        return;

    float sfac = 1.0f + (s4.x + s4.y + s4.z + s4.w) * 0.25f;

    int pz0 = pz_[0], pz1 = pz_[1];
    float wz0 = sfac*wz[0], wz1 = sfac*wz[1];
    bool band0 = (wz[0] != 0.0f) && (pz0 >= AG_Z0) && (pz0 < AG_Z0 + AG_NZ);
    bool band1 = (wz[1] != 0.0f) && (pz1 >= AG_Z0) && (pz1 < AG_Z0 + AG_NZ);

    int odd = pz0 & 1;
    float* g0base = (odd ? g_g0b : g_g0a) + (size_t)b*G0_PER_B + (pz0 - odd);

    float semv[16];
    if (band0 | band1) {
        #pragma unroll
        for (int c = 0; c < 16; c++)
            semv[c] = __ldg(&obs_b[(4+c)*NPIX + pix]) * sfac;
    }

    float* gsb = g_gs + (size_t)b*GS_PER_B*16;

    #pragma unroll
    for (int kx = 0; kx < 2; kx++) {
        #pragma unroll
        for (int ky = 0; ky < 2; ky++) {
            float wxy = wx[kx]*wy[ky];
            if (wxy == 0.0f) continue;
            int cellxy = px_[kx]*100 + py_[ky];

            atomicAdd((float2*)(g0base + cellxy*80), make_float2(wxy*wz0, wxy*wz1));

            if (band0) {
                float w = wxy*wz[0];
                float* dst = gsb + ((size_t)cellxy*AG_NZ + (pz0 - AG_Z0))*16;
                atomicAdd((float4*)(dst+ 0), make_float4(semv[ 0]*w, semv[ 1]*w, semv[ 2]*w, semv[ 3]*w));
                atomicAdd((float4*)(dst+ 4), make_float4(semv[ 4]*w, semv[ 5]*w, semv[ 6]*w, semv[ 7]*w));
                atomicAdd((float4*)(dst+ 8), make_float4(semv[ 8]*w, semv[ 9]*w, semv[10]*w, semv[11]*w));
                atomicAdd((float4*)(dst+12), make_float4(semv[12]*w, semv[13]*w, semv[14]*w, semv[15]*w));
            }
            if (band1) {
                float w = wxy*wz[1];
                float* dst = gsb + ((size_t)cellxy*AG_NZ + (pz1 - AG_Z0))*16;
                atomicAdd((float4*)(dst+ 0), make_float4(semv[ 0]*w, semv[ 1]*w, semv[ 2]*w, semv[ 3]*w));
                atomicAdd((float4*)(dst+ 4), make_float4(semv[ 4]*w, semv[ 5]*w, semv[ 6]*w, semv[ 7]*w));
                atomicAdd((float4*)(dst+ 8), make_float4(semv[ 8]*w, semv[ 9]*w, semv[10]*w, semv[11]*w));
                atomicAdd((float4*)(dst+12), make_float4(semv[12]*w, semv[13]*w, semv[14]*w, semv[15]*w));
            }
        }
    }
}

// ---------- fat kernel: splat blocks FIRST, stream backfills (R8 plain-load variant) ----------
__global__ void __launch_bounds__(256) splat_stream_kernel(const float* __restrict__ obs,
                                                           const float* __restrict__ sh,
                                                           const float* __restrict__ maps_last,
                                                           float* __restrict__ dout) {
    if (blockIdx.x < SPLAT_BLOCKS) {
        splat_body(blockIdx.x*256 + threadIdx.x, obs, sh);
    } else {
        size_t t = (size_t)(blockIdx.x - SPLAT_BLOCKS)*256 + threadIdx.x;
        float4 v = ((const float4*)maps_last)[t];
        v.x = fmaxf(v.x, 0.0f); v.y = fmaxf(v.y, 0.0f);
        v.z = fmaxf(v.z, 0.0f); v.w = fmaxf(v.w, 0.0f);
        ((float4*)(dout + OUT_MAP_OFF))[t] = v;
    }
}

// ---------- proj : g0-half and sem-half thread groups (R9 measured) ----------
__global__ void __launch_bounds__(256) proj_kernel(float* __restrict__ dout) {
    const int N4 = NB*NCELL*4;
    int t = blockIdx.x*blockDim.x + threadIdx.x;

    if (t < N4) {
        int q = t & 3;
        int cellIdx = t >> 2;
        int b   = cellIdx / NCELL;
        int cxy = cellIdx - b*NCELL;
        int x = cxy / 100, y = cxy - x*100;
        int cell = y*100 + x;

        const float* acell = g_g0a + (size_t)b*G0_PER_B + (size_t)cxy*80;
        const float* bcell = g_g0b + (size_t)b*G0_PER_B + (size_t)cxy*80;
        const float4* a4p = (const float4*)acell + q*5;
        const float4* b4p = (const float4*)bcell + q*5;

        float prev = (q == 0) ? 0.0f : bcell[q*20 - 1];

        float a_all = 0.0f, a_ag = 0.0f;
        #pragma unroll
        for (int k = 0; k < 5; k++) {
            float4 a4 = a4p[k];
            float4 b4 = b4p[k];
            int z = q*20 + k*4;
            float v0 = rintf(a4.x + prev);
            float v1 = rintf(a4.y + b4.x);
            float v2 = rintf(a4.z + b4.y);
            float v3 = rintf(a4.w + b4.z);
            prev = b4.w;
            a_all += v0 + v1 + v2 + v3;
            a_ag += (z+0 >= 13 && z+0 < 25) ? v0 : 0.0f;
            a_ag += (z+1 >= 13 && z+1 < 25) ? v1 : 0.0f;
            a_ag += (z+2 >= 13 && z+2 < 25) ? v2 : 0.0f;
            a_ag += (z+3 >= 13 && z+3 < 25) ? v3 : 0.0f;
        }

        a_all += __shfl_xor_sync(0xFFFFFFFFu, a_all, 1);
        a_all += __shfl_xor_sync(0xFFFFFFFFu, a_all, 2);
        a_ag  += __shfl_xor_sync(0xFFFFFFFFu, a_ag, 1);
        a_ag  += __shfl_xor_sync(0xFFFFFFFFu, a_ag, 2);

        if (q == 0) {
            float pm = fminf(fmaxf(a_ag, 0.0f), 1.0f);
            float pe = fminf(fmaxf(a_all, 0.0f), 1.0f);
            float* rec = g_pall + ((size_t)b*NCELL + cell)*20;
            rec[0] = pm;
            rec[1] = pe;
            dout[(size_t)b*NCELL + cell] = pm;
        }
    } else {
        int u = t - N4;
        if (u >= N4) return;
        int q = u & 3;
        int cellIdx = u >> 2;
        int b   = cellIdx / NCELL;
        int cxy = cellIdx - b*NCELL;
        int x = cxy / 100, y = cxy - x*100;
        int cell = y*100 + x;

        const float4* gsp = (const float4*)(g_gs + ((size_t)b*GS_PER_B + (size_t)cxy*AG_NZ)*16) + q;
        float4 acc = make_float4(0.f,0.f,0.f,0.f);
        #pragma unroll
        for (int zz = 0; zz < AG_NZ; zz++) {
            float4 v = gsp[zz*4];
            acc.x += rintf(v.x);
            acc.y += rintf(v.y);
            acc.z += rintf(v.z);
            acc.w += rintf(v.w);
        }

        float* rec = g_pall + ((size_t)b*NCELL + cell)*20;
        rec[2 + q*4 + 0] = fminf(fmaxf(acc.x / 5.0f, 0.0f), 1.0f);
        rec[2 + q*4 + 1] = fminf(fmaxf(acc.y / 5.0f, 0.0f), 1.0f);
        rec[2 + q*4 + 2] = fminf(fmaxf(acc.z / 5.0f, 0.0f), 1.0f);
        rec[2 + q*4 + 3] = fminf(fmaxf(acc.w / 5.0f, 0.0f), 1.0f);
        if (q == 3) {
            rec[18] = 0.0f;
            rec[19] = 0.0f;
        }
    }
}

// ---------- window pass : 2 threads/pixel (R8/R10 measured-best) ----------
__global__ void __launch_bounds__(256) map_window_kernel(const float* __restrict__ maps_last,
                                                         float* __restrict__ dout) {
    int t = blockIdx.x*blockDim.x + threadIdx.x;
    int half  = t & 1;
    int pixId = t >> 1;
    int b   = pixId / (WIN*WIN);
    int rem = pixId - b*(WIN*WIN);
    int li = rem / WIN, lj = rem - li*WIN;

    float ct = g_params[b*8+0], st = g_params[b*8+1];
    float dx = g_params[b*8+2], dy = g_params[b*8+3];
    int bi0 = (int)g_params[b*8+4], bi1 = (int)g_params[b*8+5];
    int bj0 = (int)g_params[b*8+6], bj1 = (int)g_params[b*8+7];

    int i = bi0 + li;
    int j = bj0 + lj;
    bool valid = (i <= bi1) && (j <= bj1) && (i >= 0) && (i < MC) && (j >= 0) && (j < MC);

    float xs = (float)j + dx, ys = (float)i + dy;
    float x0f = floorf(xs), y0f = floorf(ys);
    float wxb = xs - x0f, wxa = 1.0f - wxb;
    float wyb = ys - y0f, wya = 1.0f - wyb;
    int ix0 = (int)x0f, iy0 = (int)y0f;

    const float4* pall4 = (const float4*)(g_pall + (size_t)b*NCELL*20);

    float4 acc0 = make_float4(0,0,0,0), acc1 = acc0, acc2 = acc0, acc3 = acc0, acc4 = acc0;

    #pragma unroll
    for (int kk = 0; kk < 2; kk++) {
        int k  = half*2 + kk;
        int tx = ix0 + (k & 1);
        int ty = iy0 + (k >> 1);
        bool tvalid = valid && (tx >= 0) && (tx < MC) && (ty >= 0) && (ty < MC);
        float twk = ((k & 1) ? wxb : wxa) * ((k >> 1) ? wyb : wya);

        float gxr = -1.0f + (float)tx * (2.0f/479.0f);
        float gyr = -1.0f + (float)ty * (2.0f/479.0f);
        float xr = ((ct*gxr - st*gyr) + 1.0f) * 239.5f;
        float yr = ((st*gxr + ct*gyr) + 1.0f) * 239.5f;
        float rx0f = floorf(xr), ry0f = floorf(yr);
        float rb = xr - rx0f, ra = 1.0f - rb;
        float rd = yr - ry0f, rc = 1.0f - rd;
        int rx0 = (int)rx0f, ry0 = (int)ry0f;

        #pragma unroll
        for (int s = 0; s < 4; s++) {
            int ix = rx0 + (s & 1);
            int iy = ry0 + (s >> 1);
            bool in = tvalid && (ix >= 190) && (ix < 290) && (iy >= 240) && (iy < 340);
            if (in) {
                float rw = ((s & 1) ? rb : ra) * ((s >> 1) ? rd : rc);
                float w = twk * rw;
                const float4* rp = pall4 + ((iy - 240)*100 + (ix - 190))*5;
                float4 r0 = rp[0], r1 = rp[1], r2 = rp[2], r3 = rp[3], r4 = rp[4];
                acc0.x += w*r0.x; acc0.y += w*r0.y; acc0.z += w*r0.z; acc0.w += w*r0.w;
                acc1.x += w*r1.x; acc1.y += w*r1.y; acc1.z += w*r1.z; acc1.w += w*r1.w;
                acc2.x += w*r2.x; acc2.y += w*r2.y; acc2.z += w*r2.z; acc2.w += w*r2.w;
                acc3.x += w*r3.x; acc3.y += w*r3.y; acc3.z += w*r3.z; acc3.w += w*r3.w;
                acc4.x += w*r4.x; acc4.y += w*r4.y;
            }
        }
    }

    acc0.x += __shfl_xor_sync(0xFFFFFFFFu, acc0.x, 1);
    acc0.y += __shfl_xor_sync(0xFFFFFFFFu, acc0.y, 1);
    acc0.z += __shfl_xor_sync(0xFFFFFFFFu, acc0.z, 1);
    acc0.w += __shfl_xor_sync(0xFFFFFFFFu, acc0.w, 1);
    acc1.x += __shfl_xor_sync(0xFFFFFFFFu, acc1.x, 1);
    acc1.y += __shfl_xor_sync(0xFFFFFFFFu, acc1.y, 1);
    acc1.z += __shfl_xor_sync(0xFFFFFFFFu, acc1.z, 1);
    acc1.w += __shfl_xor_sync(0xFFFFFFFFu, acc1.w, 1);
    acc2.x += __shfl_xor_sync(0xFFFFFFFFu, acc2.x, 1);
    acc2.y += __shfl_xor_sync(0xFFFFFFFFu, acc2.y, 1);
    acc2.z += __shfl_xor_sync(0xFFFFFFFFu, acc2.z, 1);
    acc2.w += __shfl_xor_sync(0xFFFFFFFFu, acc2.w, 1);
    acc3.x += __shfl_xor_sync(0xFFFFFFFFu, acc3.x, 1);
    acc3.y += __shfl_xor_sync(0xFFFFFFFFu, acc3.y, 1);
    acc3.z += __shfl_xor_sync(0xFFFFFFFFu, acc3.z, 1);
    acc3.w += __shfl_xor_sync(0xFFFFFFFFu, acc3.w, 1);
    acc4.x += __shfl_xor_sync(0xFFFFFFFFu, acc4.x, 1);
    acc4.y += __shfl_xor_sync(0xFFFFFFFFu, acc4.y, 1);

    if (half != 0 || !valid) return;

    size_t base = (size_t)b*C_OBS*MC*MC + (size_t)i*MC + j;
    const float* mlp  = maps_last + base;
    float*       outp = dout + OUT_MAP_OFF + base;
    const size_t S = (size_t)MC*MC;

    outp[0]    = fmaxf(mlp[0],    acc0.x);
    outp[S]    = fmaxf(mlp[S],    acc0.y);
    outp[4*S]  = fmaxf(mlp[4*S],  acc0.z);
    outp[5*S]  = fmaxf(mlp[5*S],  acc0.w);
    outp[6*S]  = fmaxf(mlp[6*S],  acc1.x);
    outp[7*S]  = fmaxf(mlp[7*S],  acc1.y);
    outp[8*S]  = fmaxf(mlp[8*S],  acc1.z);
    outp[9*S]  = fmaxf(mlp[9*S],  acc1.w);
    outp[10*S] = fmaxf(mlp[10*S], acc2.x);
    outp[11*S] = fmaxf(mlp[11*S], acc2.y);
    outp[12*S] = fmaxf(mlp[12*S], acc2.z);
    outp[13*S] = fmaxf(mlp[13*S], acc2.w);
    outp[14*S] = fmaxf(mlp[14*S], acc3.x);
    outp[15*S] = fmaxf(mlp[15*S], acc3.y);
    outp[16*S] = fmaxf(mlp[16*S], acc3.z);
    outp[17*S] = fmaxf(mlp[17*S], acc3.w);
    outp[18*S] = fmaxf(mlp[18*S], acc4.x);
    outp[19*S] = fmaxf(mlp[19*S], acc4.y);
}

extern "C" void kernel_launch(void* const* d_in, const int* in_sizes, int n_in,
                              void* d_out, int out_size) {
    const float* obs        = (const float*)d_in[0];
    const float* pose_obs   = (const float*)d_in[1];
    const float* maps_last  = (const float*)d_in[2];
    const float* poses_last = (const float*)d_in[3];
    const float* sh         = (const float*)d_in[4];
    float* out = (float*)d_out;

    zero_pose_kernel<<<(NB*GS_PER_B*16/4 + 255)/256, 256>>>(pose_obs, poses_last, out);
    splat_stream_kernel<<<FAT_BLOCKS, 256>>>(obs, sh, maps_last, out);
    proj_kernel<<<(NB*NCELL*8 + 255)/256, 256>>>(out);
    map_window_kernel<<<NB*WIN*WIN*2/256, 256>>>(maps_last, out);
}

// round 14
// speedup vs baseline: 1.0961x; 1.0145x over previous
#include <cuda_runtime.h>
#include <math.h>

#define NB 4
#define FH 480
#define FW 640
#define NPIX (FH*FW)
#define NSEM 16
#define C_OBS 20
#define VR 100
#define HZ 80
#define MC 480
#define NCELL (VR*VR)          // 10000
#define G0_PER_B (NCELL*HZ)    // 800000
#define AG_Z0 13
#define AG_NZ 12
#define GS_PER_B (NCELL*AG_NZ) // 120000
#define WIN 160

#define SPLAT_BLOCKS (NB*NPIX/256)                 // 4800
#define STREAM_N4    ((size_t)NB*C_OBS*MC*MC/4)    // 4,608,000 float4
#define STREAM_BLOCKS ((int)(STREAM_N4/256))       // 18000
#define FAT_BLOCKS   (SPLAT_BLOCKS + STREAM_BLOCKS)

#define WINDOW_BLOCKS (NB*WIN*WIN*2/256)           // 800
#define ZEROF_BLOCKS ((NB*GS_PER_B*16/4 + 255)/256) // 7500 (covers gs; g0a/b smaller)
#define WZ_BLOCKS    (WINDOW_BLOCKS + ZEROF_BLOCKS)

// Output layout: fp_map_pred (NB*NCELL) | map_pred (NB*20*480*480) | poses (12) | poses (12)
#define OUT_MAP_OFF ((size_t)NB*NCELL)
#define OUT_POSE_OFF (OUT_MAP_OFF + (size_t)NB*C_OBS*MC*MC)

// ---------- scratch (zero at module load; window_zero re-zeros for next replay) ----------
__device__ __align__(16) float g_g0a[NB*G0_PER_B];   // ch-0, even-parity pairs; slot z = voxel z
__device__ __align__(16) float g_g0b[NB*G0_PER_B];   // ch-0, odd-parity pairs;  slot z = voxel z+1
__device__ __align__(16) float g_gs[NB*GS_PER_B*16]; // sem voxels [b][(x*100+y)*12+(z-13)][16]
__device__ __align__(16) float g_pall[NB*NCELL*20];  // interleaved proj: [b][y*100+x][20]
__device__ float g_params[NB*8];
__device__ float g_fcal;

// ---------- pose update + sampling params + focal constant (1 tiny block) ----------
__global__ void pose_kernel(const float* __restrict__ pose_obs,
                            const float* __restrict__ poses_last,
                            float* __restrict__ dout) {
    if (threadIdx.x == 0) {
        g_fcal = (float)(320.0 / tan(39.5 * 3.14159265358979323846 / 180.0));
    }
    int b = threadIdx.x;
    if (b >= NB) return;
    const float DEGf = (float)57.29577951308232;
    float pl0 = poses_last[b*3+0], pl1 = poses_last[b*3+1], pl2 = poses_last[b*3+2];
    float po0 = pose_obs[b*3+0],  po1 = pose_obs[b*3+1],  po2 = pose_obs[b*3+2];
    float t0 = pl2 / DEGf;
    float s0 = sinf(t0), c0 = cosf(t0);
    float y_new = pl1 + po0*s0 + po1*c0;
    float x_new = pl0 + po0*c0 - po1*s0;
    float t_new = pl2 + po2*DEGf;
    t_new = fmodf(t_new - 180.0f, 360.0f) + 180.0f;
    t_new = fmodf(t_new + 180.0f, 360.0f) - 180.0f;

    dout[OUT_POSE_OFF      + b*3+0] = x_new;
    dout[OUT_POSE_OFF      + b*3+1] = y_new;
    dout[OUT_POSE_OFF      + b*3+2] = t_new;
    dout[OUT_POSE_OFF + 12 + b*3+0] = x_new;
    dout[OUT_POSE_OFF + 12 + b*3+1] = y_new;
    dout[OUT_POSE_OFF + 12 + b*3+2] = t_new;

    float stx = -(x_new*100.0f/5.0f - 240.0f)/240.0f;
    float sty = -(y_new*100.0f/5.0f - 240.0f)/240.0f;
    float stt = (90.0f - t_new) * (float)0.017453292519943295;
    float ct = cosf(stt), st = sinf(stt);
    float dx = stx * 239.5f;
    float dy = sty * 239.5f;
    g_params[b*8+0] = ct;
    g_params[b*8+1] = st;
    g_params[b*8+2] = dx;
    g_params[b*8+3] = dy;

    float u0 = 189.0f/239.5f - 1.0f, u1 = 290.0f/239.5f - 1.0f;
    float v0 = 239.0f/239.5f - 1.0f, v1 = 340.0f/239.5f - 1.0f;
    float gxmin = 1e9f, gxmax = -1e9f, gymin = 1e9f, gymax = -1e9f;
    #pragma unroll
    for (int k = 0; k < 4; k++) {
        float u = (k & 1) ? u1 : u0;
        float v = (k & 2) ? v1 : v0;
        float gx = ct*u + st*v;
        float gy = -st*u + ct*v;
        gxmin = fminf(gxmin, gx); gxmax = fmaxf(gxmax, gx);
        gymin = fminf(gymin, gy); gymax = fmaxf(gymax, gy);
    }
    float txmin = (gxmin + 1.0f)*239.5f, txmax = (gxmax + 1.0f)*239.5f;
    float tymin = (gymin + 1.0f)*239.5f, tymax = (gymax + 1.0f)*239.5f;
    g_params[b*8+4] = floorf(tymin - dy - 3.0f);
    g_params[b*8+5] = ceilf (tymax - dy + 3.0f);
    g_params[b*8+6] = floorf(txmin - dx - 3.0f);
    g_params[b*8+7] = ceilf (txmax - dx + 3.0f);
}

// ---------- splat body ----------
__device__ __forceinline__ void splat_body(int t, const float* __restrict__ obs,
                                           const float* __restrict__ sh) {
    int b   = t / NPIX;
    int pix = t - b*NPIX;
    int i   = pix / FW;
    int j   = pix - i*FW;

    const float* obs_b = obs + (size_t)b*C_OBS*NPIX;
    float depth = __ldg(&obs_b[3*NPIX + pix]);
    float4 s4   = __ldg(&((const float4*)sh)[(size_t)b*NPIX + pix]);

    float fc = g_fcal;
    float X = ((float)j - 319.5f) * depth / fc;
    float Z = (239.5f - (float)i) * depth / fc;

    float xn = ((X + 250.0f)/5.0f - 50.0f)/100.0f*2.0f;
    float yn = (depth/5.0f - 50.0f)/100.0f*2.0f;
    float zn = ((Z + 88.0f)/5.0f - 32.0f)/80.0f*2.0f;
    xn = fminf(fmaxf(xn, -1.0f), 1.0f);
    yn = fminf(fmaxf(yn, -1.0f), 1.0f);
    zn = fminf(fmaxf(zn, -1.0f), 1.0f);

    float posx = xn*50.0f + 50.0f;
    float posy = yn*50.0f + 50.0f;
    float posz = zn*40.0f + 40.0f;

    float fx = floorf(posx), fy = floorf(posy), fz = floorf(posz);
    float wx[2], wy[2], wz[2];
    int   px_[2], py_[2], pz_[2];
    #pragma unroll
    for (int k = 0; k < 2; k++) {
        float p;
        p = fx + (float)k; { bool s = (p > 0.0f && p < 100.0f); wx[k] = s ? (1.0f - fabsf(posx - p)) : 0.0f; px_[k] = (int)p; }
        p = fy + (float)k; { bool s = (p > 0.0f && p < 100.0f); wy[k] = s ? (1.0f - fabsf(posy - p)) : 0.0f; py_[k] = (int)p; }
        p = fz + (float)k; { bool s = (p > 0.0f && p <  80.0f); wz[k] = s ? (1.0f - fabsf(posz - p)) : 0.0f; pz_[k] = (int)p; }
    }
    if ((wx[0]==0.0f && wx[1]==0.0f) || (wy[0]==0.0f && wy[1]==0.0f) || (wz[0]==0.0f && wz[1]==0.0f))
        return;

    float sfac = 1.0f + (s4.x + s4.y + s4.z + s4.w) * 0.25f;

    int pz0 = pz_[0], pz1 = pz_[1];
    float wz0 = sfac*wz[0], wz1 = sfac*wz[1];
    bool band0 = (wz[0] != 0.0f) && (pz0 >= AG_Z0) && (pz0 < AG_Z0 + AG_NZ);
    bool band1 = (wz[1] != 0.0f) && (pz1 >= AG_Z0) && (pz1 < AG_Z0 + AG_NZ);

    int odd = pz0 & 1;
    float* g0base = (odd ? g_g0b : g_g0a) + (size_t)b*G0_PER_B + (pz0 - odd);

    float semv[16];
    if (band0 | band1) {
        #pragma unroll
        for (int c = 0; c < 16; c++)
            semv[c] = __ldg(&obs_b[(4+c)*NPIX + pix]) * sfac;
    }

    float* gsb = g_gs + (size_t)b*GS_PER_B*16;

    #pragma unroll
    for (int kx = 0; kx < 2; kx++) {
        #pragma unroll
        for (int ky = 0; ky < 2; ky++) {
            float wxy = wx[kx]*wy[ky];
            if (wxy == 0.0f) continue;
            int cellxy = px_[kx]*100 + py_[ky];

            atomicAdd((float2*)(g0base + cellxy*80), make_float2(wxy*wz0, wxy*wz1));

            if (band0) {
                float w = wxy*wz[0];
                float* dst = gsb + ((size_t)cellxy*AG_NZ + (pz0 - AG_Z0))*16;
                atomicAdd((float4*)(dst+ 0), make_float4(semv[ 0]*w, semv[ 1]*w, semv[ 2]*w, semv[ 3]*w));
                atomicAdd((float4*)(dst+ 4), make_float4(semv[ 4]*w, semv[ 5]*w, semv[ 6]*w, semv[ 7]*w));
                atomicAdd((float4*)(dst+ 8), make_float4(semv[ 8]*w, semv[ 9]*w, semv[10]*w, semv[11]*w));
                atomicAdd((float4*)(dst+12), make_float4(semv[12]*w, semv[13]*w, semv[14]*w, semv[15]*w));
            }
            if (band1) {
                float w = wxy*wz[1];
                float* dst = gsb + ((size_t)cellxy*AG_NZ + (pz1 - AG_Z0))*16;
                atomicAdd((float4*)(dst+ 0), make_float4(semv[ 0]*w, semv[ 1]*w, semv[ 2]*w, semv[ 3]*w));
                atomicAdd((float4*)(dst+ 4), make_float4(semv[ 4]*w, semv[ 5]*w, semv[ 6]*w, semv[ 7]*w));
                atomicAdd((float4*)(dst+ 8), make_float4(semv[ 8]*w, semv[ 9]*w, semv[10]*w, semv[11]*w));
                atomicAdd((float4*)(dst+12), make_float4(semv[12]*w, semv[13]*w, semv[14]*w, semv[15]*w));
            }
        }
    }
}

// ---------- fat kernel: splat blocks FIRST, stream backfills (R8 measured) ----------
__global__ void __launch_bounds__(256) splat_stream_kernel(const float* __restrict__ obs,
                                                           const float* __restrict__ sh,
                                                           const float* __restrict__ maps_last,
                                                           float* __restrict__ dout) {
    if (blockIdx.x < SPLAT_BLOCKS) {
        splat_body(blockIdx.x*256 + threadIdx.x, obs, sh);
    } else {
        size_t t = (size_t)(blockIdx.x - SPLAT_BLOCKS)*256 + threadIdx.x;
        float4 v = ((const float4*)maps_last)[t];
        v.x = fmaxf(v.x, 0.0f); v.y = fmaxf(v.y, 0.0f);
        v.z = fmaxf(v.z, 0.0f); v.w = fmaxf(v.w, 0.0f);
        ((float4*)(dout + OUT_MAP_OFF))[t] = v;
    }
}

// ---------- proj : g0-half and sem-half thread groups (R9 measured) ----------
__global__ void __launch_bounds__(256) proj_kernel(float* __restrict__ dout) {
    const int N4 = NB*NCELL*4;
    int t = blockIdx.x*blockDim.x + threadIdx.x;

    if (t < N4) {
        int q = t & 3;
        int cellIdx = t >> 2;
        int b   = cellIdx / NCELL;
        int cxy = cellIdx - b*NCELL;
        int x = cxy / 100, y = cxy - x*100;
        int cell = y*100 + x;

        const float* acell = g_g0a + (size_t)b*G0_PER_B + (size_t)cxy*80;
        const float* bcell = g_g0b + (size_t)b*G0_PER_B + (size_t)cxy*80;
        const float4* a4p = (const float4*)acell + q*5;
        const float4* b4p = (const float4*)bcell + q*5;

        float prev = (q == 0) ? 0.0f : bcell[q*20 - 1];

        float a_all = 0.0f, a_ag = 0.0f;
        #pragma unroll
        for (int k = 0; k < 5; k++) {
            float4 a4 = a4p[k];
            float4 b4 = b4p[k];
            int z = q*20 + k*4;
            float v0 = rintf(a4.x + prev);
            float v1 = rintf(a4.y + b4.x);
            float v2 = rintf(a4.z + b4.y);
            float v3 = rintf(a4.w + b4.z);
            prev = b4.w;
            a_all += v0 + v1 + v2 + v3;
            a_ag += (z+0 >= 13 && z+0 < 25) ? v0 : 0.0f;
            a_ag += (z+1 >= 13 && z+1 < 25) ? v1 : 0.0f;
            a_ag += (z+2 >= 13 && z+2 < 25) ? v2 : 0.0f;
            a_ag += (z+3 >= 13 && z+3 < 25) ? v3 : 0.0f;
        }

        a_all += __shfl_xor_sync(0xFFFFFFFFu, a_all, 1);
        a_all += __shfl_xor_sync(0xFFFFFFFFu, a_all, 2);
        a_ag  += __shfl_xor_sync(0xFFFFFFFFu, a_ag, 1);
        a_ag  += __shfl_xor_sync(0xFFFFFFFFu, a_ag, 2);

        if (q == 0) {
            float pm = fminf(fmaxf(a_ag, 0.0f), 1.0f);
            float pe = fminf(fmaxf(a_all, 0.0f), 1.0f);
            float* rec = g_pall + ((size_t)b*NCELL + cell)*20;
            rec[0] = pm;
            rec[1] = pe;
            dout[(size_t)b*NCELL + cell] = pm;
        }
    } else {
        int u = t - N4;
        if (u >= N4) return;
        int q = u & 3;
        int cellIdx = u >> 2;
        int b   = cellIdx / NCELL;
        int cxy = cellIdx - b*NCELL;
        int x = cxy / 100, y = cxy - x*100;
        int cell = y*100 + x;

        const float4* gsp = (const float4*)(g_gs + ((size_t)b*GS_PER_B + (size_t)cxy*AG_NZ)*16) + q;
        float4 acc = make_float4(0.f,0.f,0.f,0.f);
        #pragma unroll
        for (int zz = 0; zz < AG_NZ; zz++) {
            float4 v = gsp[zz*4];
            acc.x += rintf(v.x);
            acc.y += rintf(v.y);
            acc.z += rintf(v.z);
            acc.w += rintf(v.w);
        }

        float* rec = g_pall + ((size_t)b*NCELL + cell)*20;
        rec[2 + q*4 + 0] = fminf(fmaxf(acc.x / 5.0f, 0.0f), 1.0f);
        rec[2 + q*4 + 1] = fminf(fmaxf(acc.y / 5.0f, 0.0f), 1.0f);
        rec[2 + q*4 + 2] = fminf(fmaxf(acc.z / 5.0f, 0.0f), 1.0f);
        rec[2 + q*4 + 3] = fminf(fmaxf(acc.w / 5.0f, 0.0f), 1.0f);
        if (q == 3) {
            rec[18] = 0.0f;
            rec[19] = 0.0f;
        }
    }
}

// ---------- window body : 2 threads/pixel (R8/R10 measured-best) ----------
__device__ __forceinline__ void window_body(int t, const float* __restrict__ maps_last,
                                            float* __restrict__ dout) {
    int half  = t & 1;
    int pixId = t >> 1;
    int b   = pixId / (WIN*WIN);
    int rem = pixId - b*(WIN*WIN);
    int li = rem / WIN, lj = rem - li*WIN;

    float ct = g_params[b*8+0], st = g_params[b*8+1];
    float dx = g_params[b*8+2], dy = g_params[b*8+3];
    int bi0 = (int)g_params[b*8+4], bi1 = (int)g_params[b*8+5];
    int bj0 = (int)g_params[b*8+6], bj1 = (int)g_params[b*8+7];

    int i = bi0 + li;
    int j = bj0 + lj;
    bool valid = (i <= bi1) && (j <= bj1) && (i >= 0) && (i < MC) && (j >= 0) && (j < MC);

    float xs = (float)j + dx, ys = (float)i + dy;
    float x0f = floorf(xs), y0f = floorf(ys);
    float wxb = xs - x0f, wxa = 1.0f - wxb;
    float wyb = ys - y0f, wya = 1.0f - wyb;
    int ix0 = (int)x0f, iy0 = (int)y0f;

    const float4* pall4 = (const float4*)(g_pall + (size_t)b*NCELL*20);

    float4 acc0 = make_float4(0,0,0,0), acc1 = acc0, acc2 = acc0, acc3 = acc0, acc4 = acc0;

    #pragma unroll
    for (int kk = 0; kk < 2; kk++) {
        int k  = half*2 + kk;
        int tx = ix0 + (k & 1);
        int ty = iy0 + (k >> 1);
        bool tvalid = valid && (tx >= 0) && (tx < MC) && (ty >= 0) && (ty < MC);
        float twk = ((k & 1) ? wxb : wxa) * ((k >> 1) ? wyb : wya);

        float gxr = -1.0f + (float)tx * (2.0f/479.0f);
        float gyr = -1.0f + (float)ty * (2.0f/479.0f);
        float xr = ((ct*gxr - st*gyr) + 1.0f) * 239.5f;
        float yr = ((st*gxr + ct*gyr) + 1.0f) * 239.5f;
        float rx0f = floorf(xr), ry0f = floorf(yr);
        float rb = xr - rx0f, ra = 1.0f - rb;
        float rd = yr - ry0f, rc = 1.0f - rd;
        int rx0 = (int)rx0f, ry0 = (int)ry0f;

        #pragma unroll
        for (int s = 0; s < 4; s++) {
            int ix = rx0 + (s & 1);
            int iy = ry0 + (s >> 1);
            bool in = tvalid && (ix >= 190) && (ix < 290) && (iy >= 240) && (iy < 340);
            if (in) {
                float rw = ((s & 1) ? rb : ra) * ((s >> 1) ? rd : rc);
                float w = twk * rw;
                const float4* rp = pall4 + ((iy - 240)*100 + (ix - 190))*5;
                float4 r0 = rp[0], r1 = rp[1], r2 = rp[2], r3 = rp[3], r4 = rp[4];
                acc0.x += w*r0.x; acc0.y += w*r0.y; acc0.z += w*r0.z; acc0.w += w*r0.w;
                acc1.x += w*r1.x; acc1.y += w*r1.y; acc1.z += w*r1.z; acc1.w += w*r1.w;
                acc2.x += w*r2.x; acc2.y += w*r2.y; acc2.z += w*r2.z; acc2.w += w*r2.w;
                acc3.x += w*r3.x; acc3.y += w*r3.y; acc3.z += w*r3.z; acc3.w += w*r3.w;
                acc4.x += w*r4.x; acc4.y += w*r4.y;
            }
        }
    }

    acc0.x += __shfl_xor_sync(0xFFFFFFFFu, acc0.x, 1);
    acc0.y += __shfl_xor_sync(0xFFFFFFFFu, acc0.y, 1);
    acc0.z += __shfl_xor_sync(0xFFFFFFFFu, acc0.z, 1);
    acc0.w += __shfl_xor_sync(0xFFFFFFFFu, acc0.w, 1);
    acc1.x += __shfl_xor_sync(0xFFFFFFFFu, acc1.x, 1);
    acc1.y += __shfl_xor_sync(0xFFFFFFFFu, acc1.y, 1);
    acc1.z += __shfl_xor_sync(0xFFFFFFFFu, acc1.z, 1);
    acc1.w += __shfl_xor_sync(0xFFFFFFFFu, acc1.w, 1);
    acc2.x += __shfl_xor_sync(0xFFFFFFFFu, acc2.x, 1);
    acc2.y += __shfl_xor_sync(0xFFFFFFFFu, acc2.y, 1);
    acc2.z += __shfl_xor_sync(0xFFFFFFFFu, acc2.z, 1);
    acc2.w += __shfl_xor_sync(0xFFFFFFFFu, acc2.w, 1);
    acc3.x += __shfl_xor_sync(0xFFFFFFFFu, acc3.x, 1);
    acc3.y += __shfl_xor_sync(0xFFFFFFFFu, acc3.y, 1);
    acc3.z += __shfl_xor_sync(0xFFFFFFFFu, acc3.z, 1);
    acc3.w += __shfl_xor_sync(0xFFFFFFFFu, acc3.w, 1);
    acc4.x += __shfl_xor_sync(0xFFFFFFFFu, acc4.x, 1);
    acc4.y += __shfl_xor_sync(0xFFFFFFFFu, acc4.y, 1);

    if (half != 0 || !valid) return;

    size_t base = (size_t)b*C_OBS*MC*MC + (size_t)i*MC + j;
    const float* mlp  = maps_last + base;
    float*       outp = dout + OUT_MAP_OFF + base;
    const size_t S = (size_t)MC*MC;

    outp[0]    = fmaxf(mlp[0],    acc0.x);
    outp[S]    = fmaxf(mlp[S],    acc0.y);
    outp[4*S]  = fmaxf(mlp[4*S],  acc0.z);
    outp[5*S]  = fmaxf(mlp[5*S],  acc0.w);
    outp[6*S]  = fmaxf(mlp[6*S],  acc1.x);
    outp[7*S]  = fmaxf(mlp[7*S],  acc1.y);
    outp[8*S]  = fmaxf(mlp[8*S],  acc1.z);
    outp[9*S]  = fmaxf(mlp[9*S],  acc1.w);
    outp[10*S] = fmaxf(mlp[10*S], acc2.x);
    outp[11*S] = fmaxf(mlp[11*S], acc2.y);
    outp[12*S] = fmaxf(mlp[12*S], acc2.z);
    outp[13*S] = fmaxf(mlp[13*S], acc2.w);
    outp[14*S] = fmaxf(mlp[14*S], acc3.x);
    outp[15*S] = fmaxf(mlp[15*S], acc3.y);
    outp[16*S] = fmaxf(mlp[16*S], acc3.z);
    outp[17*S] = fmaxf(mlp[17*S], acc3.w);
    outp[18*S] = fmaxf(mlp[18*S], acc4.x);
    outp[19*S] = fmaxf(mlp[19*S], acc4.y);
}

// ---------- window (latency-bound, first) + scratch re-zero for next replay (DRAM, backfill) ----------
// proj has already consumed the scratch; zeroing here prepares the next graph
// replay (first execution relies on module-load zero-init of __device__ globals).
__global__ void __launch_bounds__(256) window_zero_kernel(const float* __restrict__ maps_last,
                                                          float* __restrict__ dout) {
    if (blockIdx.x < WINDOW_BLOCKS) {
        window_body(blockIdx.x*256 + threadIdx.x, maps_last, dout);
        return;
    }
    int t = (blockIdx.x - WINDOW_BLOCKS)*256 + threadIdx.x;
    float4 z = make_float4(0.f,0.f,0.f,0.f);
    const int n0 = NB*G0_PER_B/4;       // 800000
    const int n1 = NB*GS_PER_B*16/4;    // 1920000
    if (t < n0) ((float4*)g_g0a)[t] = z;
    if (t < n0) ((float4*)g_g0b)[t] = z;
    if (t < n1) ((float4*)g_gs)[t] = z;
}

extern "C" void kernel_launch(void* const* d_in, const int* in_sizes, int n_in,
                              void* d_out, int out_size) {
    const float* obs        = (const float*)d_in[0];
    const float* pose_obs   = (const float*)d_in[1];
    const float* maps_last  = (const float*)d_in[2];
    const float* poses_last = (const float*)d_in[3];
    const float* sh         = (const float*)d_in[4];
    float* out = (float*)d_out;

    pose_kernel<<<1, 32>>>(pose_obs, poses_last, out);
    splat_stream_kernel<<<FAT_BLOCKS, 256>>>(obs, sh, maps_last, out);
    proj_kernel<<<(NB*NCELL*8 + 255)/256, 256>>>(out);
    window_zero_kernel<<<WZ_BLOCKS, 256>>>(maps_last, out);
}

// round 15
// speedup vs baseline: 1.1296x; 1.0305x over previous
#include <cuda_runtime.h>
#include <math.h>

#define NB 4
#define FH 480
#define FW 640
#define NPIX (FH*FW)
#define NSEM 16
#define C_OBS 20
#define VR 100
#define HZ 80
#define MC 480
#define NCELL (VR*VR)          // 10000
#define G0_PER_B (NCELL*HZ)    // 800000
#define AG_Z0 13
#define AG_NZ 12
#define GS_PER_B (NCELL*AG_NZ) // 120000
#define WIN 160

#define SPLAT_BLOCKS (NB*NPIX/256)                 // 4800
#define STREAM_N4    ((size_t)NB*C_OBS*MC*MC/4)    // 4,608,000 float4
#define STREAM_BLOCKS ((int)(STREAM_N4/256))       // 18000
#define FAT_BLOCKS   (SPLAT_BLOCKS + STREAM_BLOCKS)

#define WINDOW_BLOCKS (NB*WIN*WIN*2/256)           // 800
#define ZEROF_BLOCKS ((NB*GS_PER_B*16/4 + 255)/256) // 7500
#define WZ_BLOCKS    (WINDOW_BLOCKS + ZEROF_BLOCKS)

// Output layout: fp_map_pred (NB*NCELL) | map_pred (NB*20*480*480) | poses (12) | poses (12)
#define OUT_MAP_OFF ((size_t)NB*NCELL)
#define OUT_POSE_OFF (OUT_MAP_OFF + (size_t)NB*C_OBS*MC*MC)

// ---------- scratch (zero at module load; window_zero re-zeros for next replay) ----------
__device__ __align__(16) float g_g0a[NB*G0_PER_B];   // ch-0, even-parity pairs; slot z = voxel z
__device__ __align__(16) float g_g0b[NB*G0_PER_B];   // ch-0, odd-parity pairs;  slot z = voxel z+1
__device__ __align__(16) float g_gs[NB*GS_PER_B*16]; // sem voxels [b][(x*100+y)*12+(z-13)][16]
__device__ __align__(16) float g_pall[NB*NCELL*20];  // interleaved proj: [b][y*100+x][20]
__device__ float g_params[NB*8];
__device__ float g_fcal;

// ---------- pose update + sampling params + focal constant (1 tiny block) ----------
__global__ void pose_kernel(const float* __restrict__ pose_obs,
                            const float* __restrict__ poses_last,
                            float* __restrict__ dout) {
    if (threadIdx.x == 0) {
        g_fcal = (float)(320.0 / tan(39.5 * 3.14159265358979323846 / 180.0));
    }
    int b = threadIdx.x;
    if (b >= NB) return;
    const float DEGf = (float)57.29577951308232;
    float pl0 = poses_last[b*3+0], pl1 = poses_last[b*3+1], pl2 = poses_last[b*3+2];
    float po0 = pose_obs[b*3+0],  po1 = pose_obs[b*3+1],  po2 = pose_obs[b*3+2];
    float t0 = pl2 / DEGf;
    float s0 = sinf(t0), c0 = cosf(t0);
    float y_new = pl1 + po0*s0 + po1*c0;
    float x_new = pl0 + po0*c0 - po1*s0;
    float t_new = pl2 + po2*DEGf;
    t_new = fmodf(t_new - 180.0f, 360.0f) + 180.0f;
    t_new = fmodf(t_new + 180.0f, 360.0f) - 180.0f;

    dout[OUT_POSE_OFF      + b*3+0] = x_new;
    dout[OUT_POSE_OFF      + b*3+1] = y_new;
    dout[OUT_POSE_OFF      + b*3+2] = t_new;
    dout[OUT_POSE_OFF + 12 + b*3+0] = x_new;
    dout[OUT_POSE_OFF + 12 + b*3+1] = y_new;
    dout[OUT_POSE_OFF + 12 + b*3+2] = t_new;

    float stx = -(x_new*100.0f/5.0f - 240.0f)/240.0f;
    float sty = -(y_new*100.0f/5.0f - 240.0f)/240.0f;
    float stt = (90.0f - t_new) * (float)0.017453292519943295;
    float ct = cosf(stt), st = sinf(stt);
    float dx = stx * 239.5f;
    float dy = sty * 239.5f;
    g_params[b*8+0] = ct;
    g_params[b*8+1] = st;
    g_params[b*8+2] = dx;
    g_params[b*8+3] = dy;

    float u0 = 189.0f/239.5f - 1.0f, u1 = 290.0f/239.5f - 1.0f;
    float v0 = 239.0f/239.5f - 1.0f, v1 = 340.0f/239.5f - 1.0f;
    float gxmin = 1e9f, gxmax = -1e9f, gymin = 1e9f, gymax = -1e9f;
    #pragma unroll
    for (int k = 0; k < 4; k++) {
        float u = (k & 1) ? u1 : u0;
        float v = (k & 2) ? v1 : v0;
        float gx = ct*u + st*v;
        float gy = -st*u + ct*v;
        gxmin = fminf(gxmin, gx); gxmax = fmaxf(gxmax, gx);
        gymin = fminf(gymin, gy); gymax = fmaxf(gymax, gy);
    }
    float txmin = (gxmin + 1.0f)*239.5f, txmax = (gxmax + 1.0f)*239.5f;
    float tymin = (gymin + 1.0f)*239.5f, tymax = (gymax + 1.0f)*239.5f;
    g_params[b*8+4] = floorf(tymin - dy - 3.0f);
    g_params[b*8+5] = ceilf (tymax - dy + 3.0f);
    g_params[b*8+6] = floorf(txmin - dx - 3.0f);
    g_params[b*8+7] = ceilf (txmax - dx + 3.0f);
}

// ---------- splat body ----------
__device__ __forceinline__ void splat_body(int t, const float* __restrict__ obs,
                                           const float* __restrict__ sh) {
    int b   = t / NPIX;
    int pix = t - b*NPIX;
    int i   = pix / FW;
    int j   = pix - i*FW;

    const float* obs_b = obs + (size_t)b*C_OBS*NPIX;
    float depth = __ldg(&obs_b[3*NPIX + pix]);
    float4 s4   = __ldg(&((const float4*)sh)[(size_t)b*NPIX + pix]);

    float fc = g_fcal;
    float X = ((float)j - 319.5f) * depth / fc;
    float Z = (239.5f - (float)i) * depth / fc;

    float xn = ((X + 250.0f)/5.0f - 50.0f)/100.0f*2.0f;
    float yn = (depth/5.0f - 50.0f)/100.0f*2.0f;
    float zn = ((Z + 88.0f)/5.0f - 32.0f)/80.0f*2.0f;
    xn = fminf(fmaxf(xn, -1.0f), 1.0f);
    yn = fminf(fmaxf(yn, -1.0f), 1.0f);
    zn = fminf(fmaxf(zn, -1.0f), 1.0f);

    float posx = xn*50.0f + 50.0f;
    float posy = yn*50.0f + 50.0f;
    float posz = zn*40.0f + 40.0f;

    float fx = floorf(posx), fy = floorf(posy), fz = floorf(posz);
    float wx[2], wy[2], wz[2];
    int   px_[2], py_[2], pz_[2];
    #pragma unroll
    for (int k = 0; k < 2; k++) {
        float p;
        p = fx + (float)k; { bool s = (p > 0.0f && p < 100.0f); wx[k] = s ? (1.0f - fabsf(posx - p)) : 0.0f; px_[k] = (int)p; }
        p = fy + (float)k; { bool s = (p > 0.0f && p < 100.0f); wy[k] = s ? (1.0f - fabsf(posy - p)) : 0.0f; py_[k] = (int)p; }
        p = fz + (float)k; { bool s = (p > 0.0f && p <  80.0f); wz[k] = s ? (1.0f - fabsf(posz - p)) : 0.0f; pz_[k] = (int)p; }
    }
    if ((wx[0]==0.0f && wx[1]==0.0f) || (wy[0]==0.0f && wy[1]==0.0f) || (wz[0]==0.0f && wz[1]==0.0f))
        return;

    float sfac = 1.0f + (s4.x + s4.y + s4.z + s4.w) * 0.25f;

    int pz0 = pz_[0], pz1 = pz_[1];
    float wz0 = sfac*wz[0], wz1 = sfac*wz[1];
    bool band0 = (wz[0] != 0.0f) && (pz0 >= AG_Z0) && (pz0 < AG_Z0 + AG_NZ);
    bool band1 = (wz[1] != 0.0f) && (pz1 >= AG_Z0) && (pz1 < AG_Z0 + AG_NZ);

    int odd = pz0 & 1;
    float* g0base = (odd ? g_g0b : g_g0a) + (size_t)b*G0_PER_B + (pz0 - odd);

    float semv[16];
    if (band0 | band1) {
        #pragma unroll
        for (int c = 0; c < 16; c++)
            semv[c] = __ldg(&obs_b[(4+c)*NPIX + pix]) * sfac;
    }

    float* gsb = g_gs + (size_t)b*GS_PER_B*16;

    #pragma unroll
    for (int kx = 0; kx < 2; kx++) {
        #pragma unroll
        for (int ky = 0; ky < 2; ky++) {
            float wxy = wx[kx]*wy[ky];
            if (wxy == 0.0f) continue;
            int cellxy = px_[kx]*100 + py_[ky];

            atomicAdd((float2*)(g0base + cellxy*80), make_float2(wxy*wz0, wxy*wz1));

            if (band0) {
                float w = wxy*wz[0];
                float* dst = gsb + ((size_t)cellxy*AG_NZ + (pz0 - AG_Z0))*16;
                atomicAdd((float4*)(dst+ 0), make_float4(semv[ 0]*w, semv[ 1]*w, semv[ 2]*w, semv[ 3]*w));
                atomicAdd((float4*)(dst+ 4), make_float4(semv[ 4]*w, semv[ 5]*w, semv[ 6]*w, semv[ 7]*w));
                atomicAdd((float4*)(dst+ 8), make_float4(semv[ 8]*w, semv[ 9]*w, semv[10]*w, semv[11]*w));
                atomicAdd((float4*)(dst+12), make_float4(semv[12]*w, semv[13]*w, semv[14]*w, semv[15]*w));
            }
            if (band1) {
                float w = wxy*wz[1];
                float* dst = gsb + ((size_t)cellxy*AG_NZ + (pz1 - AG_Z0))*16;
                atomicAdd((float4*)(dst+ 0), make_float4(semv[ 0]*w, semv[ 1]*w, semv[ 2]*w, semv[ 3]*w));
                atomicAdd((float4*)(dst+ 4), make_float4(semv[ 4]*w, semv[ 5]*w, semv[ 6]*w, semv[ 7]*w));
                atomicAdd((float4*)(dst+ 8), make_float4(semv[ 8]*w, semv[ 9]*w, semv[10]*w, semv[11]*w));
                atomicAdd((float4*)(dst+12), make_float4(semv[12]*w, semv[13]*w, semv[14]*w, semv[15]*w));
            }
        }
    }
}

// ---------- fat kernel: splat blocks FIRST, stream backfills with L2-bypass hints ----------
// Evict-first hints keep the 148MB stream from evicting the L2-resident 56MB
// atomic scratch that splat's REDs depend on.
__global__ void __launch_bounds__(256) splat_stream_kernel(const float* __restrict__ obs,
                                                           const float* __restrict__ sh,
                                                           const float* __restrict__ maps_last,
                                                           float* __restrict__ dout) {
    if (blockIdx.x < SPLAT_BLOCKS) {
        splat_body(blockIdx.x*256 + threadIdx.x, obs, sh);
    } else {
        size_t t = (size_t)(blockIdx.x - SPLAT_BLOCKS)*256 + threadIdx.x;
        float4 v = __ldcs(&((const float4*)maps_last)[t]);
        v.x = fmaxf(v.x, 0.0f); v.y = fmaxf(v.y, 0.0f);
        v.z = fmaxf(v.z, 0.0f); v.w = fmaxf(v.w, 0.0f);
        __stcs(&((float4*)(dout + OUT_MAP_OFF))[t], v);
    }
}

// ---------- proj : g0-half and sem-half thread groups (R9 measured) ----------
__global__ void __launch_bounds__(256) proj_kernel(float* __restrict__ dout) {
    const int N4 = NB*NCELL*4;
    int t = blockIdx.x*blockDim.x + threadIdx.x;

    if (t < N4) {
        int q = t & 3;
        int cellIdx = t >> 2;
        int b   = cellIdx / NCELL;
        int cxy = cellIdx - b*NCELL;
        int x = cxy / 100, y = cxy - x*100;
        int cell = y*100 + x;

        const float* acell = g_g0a + (size_t)b*G0_PER_B + (size_t)cxy*80;
        const float* bcell = g_g0b + (size_t)b*G0_PER_B + (size_t)cxy*80;
        const float4* a4p = (const float4*)acell + q*5;
        const float4* b4p = (const float4*)bcell + q*5;

        float prev = (q == 0) ? 0.0f : bcell[q*20 - 1];

        float a_all = 0.0f, a_ag = 0.0f;
        #pragma unroll
        for (int k = 0; k < 5; k++) {
            float4 a4 = a4p[k];
            float4 b4 = b4p[k];
            int z = q*20 + k*4;
            float v0 = rintf(a4.x + prev);
            float v1 = rintf(a4.y + b4.x);
            float v2 = rintf(a4.z + b4.y);
            float v3 = rintf(a4.w + b4.z);
            prev = b4.w;
            a_all += v0 + v1 + v2 + v3;
            a_ag += (z+0 >= 13 && z+0 < 25) ? v0 : 0.0f;
            a_ag += (z+1 >= 13 && z+1 < 25) ? v1 : 0.0f;
            a_ag += (z+2 >= 13 && z+2 < 25) ? v2 : 0.0f;
            a_ag += (z+3 >= 13 && z+3 < 25) ? v3 : 0.0f;
        }

        a_all += __shfl_xor_sync(0xFFFFFFFFu, a_all, 1);
        a_all += __shfl_xor_sync(0xFFFFFFFFu, a_all, 2);
        a_ag  += __shfl_xor_sync(0xFFFFFFFFu, a_ag, 1);
        a_ag  += __shfl_xor_sync(0xFFFFFFFFu, a_ag, 2);

        if (q == 0) {
            float pm = fminf(fmaxf(a_ag, 0.0f), 1.0f);
            float pe = fminf(fmaxf(a_all, 0.0f), 1.0f);
            float* rec = g_pall + ((size_t)b*NCELL + cell)*20;
            rec[0] = pm;
            rec[1] = pe;
            dout[(size_t)b*NCELL + cell] = pm;
        }
    } else {
        int u = t - N4;
        if (u >= N4) return;
        int q = u & 3;
        int cellIdx = u >> 2;
        int b   = cellIdx / NCELL;
        int cxy = cellIdx - b*NCELL;
        int x = cxy / 100, y = cxy - x*100;
        int cell = y*100 + x;

        const float4* gsp = (const float4*)(g_gs + ((size_t)b*GS_PER_B + (size_t)cxy*AG_NZ)*16) + q;
        float4 acc = make_float4(0.f,0.f,0.f,0.f);
        #pragma unroll
        for (int zz = 0; zz < AG_NZ; zz++) {
            float4 v = gsp[zz*4];
            acc.x += rintf(v.x);
            acc.y += rintf(v.y);
            acc.z += rintf(v.z);
            acc.w += rintf(v.w);
        }

        float* rec = g_pall + ((size_t)b*NCELL + cell)*20;
        rec[2 + q*4 + 0] = fminf(fmaxf(acc.x / 5.0f, 0.0f), 1.0f);
        rec[2 + q*4 + 1] = fminf(fmaxf(acc.y / 5.0f, 0.0f), 1.0f);
        rec[2 + q*4 + 2] = fminf(fmaxf(acc.z / 5.0f, 0.0f), 1.0f);
        rec[2 + q*4 + 3] = fminf(fmaxf(acc.w / 5.0f, 0.0f), 1.0f);
        if (q == 3) {
            rec[18] = 0.0f;
            rec[19] = 0.0f;
        }
    }
}

// ---------- window body : 2 threads/pixel (measured-best) ----------
__device__ __forceinline__ void window_body(int t, const float* __restrict__ maps_last,
                                            float* __restrict__ dout) {
    int half  = t & 1;
    int pixId = t >> 1;
    int b   = pixId / (WIN*WIN);
    int rem = pixId - b*(WIN*WIN);
    int li = rem / WIN, lj = rem - li*WIN;

    float ct = g_params[b*8+0], st = g_params[b*8+1];
    float dx = g_params[b*8+2], dy = g_params[b*8+3];
    int bi0 = (int)g_params[b*8+4], bi1 = (int)g_params[b*8+5];
    int bj0 = (int)g_params[b*8+6], bj1 = (int)g_params[b*8+7];

    int i = bi0 + li;
    int j = bj0 + lj;
    bool valid = (i <= bi1) && (j <= bj1) && (i >= 0) && (i < MC) && (j >= 0) && (j < MC);

    float xs = (float)j + dx, ys = (float)i + dy;
    float x0f = floorf(xs), y0f = floorf(ys);
    float wxb = xs - x0f, wxa = 1.0f - wxb;
    float wyb = ys - y0f, wya = 1.0f - wyb;
    int ix0 = (int)x0f, iy0 = (int)y0f;

    const float4* pall4 = (const float4*)(g_pall + (size_t)b*NCELL*20);

    float4 acc0 = make_float4(0,0,0,0), acc1 = acc0, acc2 = acc0, acc3 = acc0, acc4 = acc0;

    #pragma unroll
    for (int kk = 0; kk < 2; kk++) {
        int k  = half*2 + kk;
        int tx = ix0 + (k & 1);
        int ty = iy0 + (k >> 1);
        bool tvalid = valid && (tx >= 0) && (tx < MC) && (ty >= 0) && (ty < MC);
        float twk = ((k & 1) ? wxb : wxa) * ((k >> 1) ? wyb : wya);

        float gxr = -1.0f + (float)tx * (2.0f/479.0f);
        float gyr = -1.0f + (float)ty * (2.0f/479.0f);
        float xr = ((ct*gxr - st*gyr) + 1.0f) * 239.5f;
        float yr = ((st*gxr + ct*gyr) + 1.0f) * 239.5f;
        float rx0f = floorf(xr), ry0f = floorf(yr);
        float rb = xr - rx0f, ra = 1.0f - rb;
        float rd = yr - ry0f, rc = 1.0f - rd;
        int rx0 = (int)rx0f, ry0 = (int)ry0f;

        #pragma unroll
        for (int s = 0; s < 4; s++) {
            int ix = rx0 + (s & 1);
            int iy = ry0 + (s >> 1);
            bool in = tvalid && (ix >= 190) && (ix < 290) && (iy >= 240) && (iy < 340);
            if (in) {
                float rw = ((s & 1) ? rb : ra) * ((s >> 1) ? rd : rc);
                float w = twk * rw;
                const float4* rp = pall4 + ((iy - 240)*100 + (ix - 190))*5;
                float4 r0 = rp[0], r1 = rp[1], r2 = rp[2], r3 = rp[3], r4 = rp[4];
                acc0.x += w*r0.x; acc0.y += w*r0.y; acc0.z += w*r0.z; acc0.w += w*r0.w;
                acc1.x += w*r1.x; acc1.y += w*r1.y; acc1.z += w*r1.z; acc1.w += w*r1.w;
                acc2.x += w*r2.x; acc2.y += w*r2.y; acc2.z += w*r2.z; acc2.w += w*r2.w;
                acc3.x += w*r3.x; acc3.y += w*r3.y; acc3.z += w*r3.z; acc3.w += w*r3.w;
                acc4.x += w*r4.x; acc4.y += w*r4.y;
            }
        }
    }

    acc0.x += __shfl_xor_sync(0xFFFFFFFFu, acc0.x, 1);
    acc0.y += __shfl_xor_sync(0xFFFFFFFFu, acc0.y, 1);
    acc0.z += __shfl_xor_sync(0xFFFFFFFFu, acc0.z, 1);
    acc0.w += __shfl_xor_sync(0xFFFFFFFFu, acc0.w, 1);
    acc1.x += __shfl_xor_sync(0xFFFFFFFFu, acc1.x, 1);
    acc1.y += __shfl_xor_sync(0xFFFFFFFFu, acc1.y, 1);
    acc1.z += __shfl_xor_sync(0xFFFFFFFFu, acc1.z, 1);
    acc1.w += __shfl_xor_sync(0xFFFFFFFFu, acc1.w, 1);
    acc2.x += __shfl_xor_sync(0xFFFFFFFFu, acc2.x, 1);
    acc2.y += __shfl_xor_sync(0xFFFFFFFFu, acc2.y, 1);
    acc2.z += __shfl_xor_sync(0xFFFFFFFFu, acc2.z, 1);
    acc2.w += __shfl_xor_sync(0xFFFFFFFFu, acc2.w, 1);
    acc3.x += __shfl_xor_sync(0xFFFFFFFFu, acc3.x, 1);
    acc3.y += __shfl_xor_sync(0xFFFFFFFFu, acc3.y, 1);
    acc3.z += __shfl_xor_sync(0xFFFFFFFFu, acc3.z, 1);
    acc3.w += __shfl_xor_sync(0xFFFFFFFFu, acc3.w, 1);
    acc4.x += __shfl_xor_sync(0xFFFFFFFFu, acc4.x, 1);
    acc4.y += __shfl_xor_sync(0xFFFFFFFFu, acc4.y, 1);

    if (half != 0 || !valid) return;

    size_t base = (size_t)b*C_OBS*MC*MC + (size_t)i*MC + j;
    const float* mlp  = maps_last + base;
    float*       outp = dout + OUT_MAP_OFF + base;
    const size_t S = (size_t)MC*MC;

    outp[0]    = fmaxf(mlp[0],    acc0.x);
    outp[S]    = fmaxf(mlp[S],    acc0.y);
    outp[4*S]  = fmaxf(mlp[4*S],  acc0.z);
    outp[5*S]  = fmaxf(mlp[5*S],  acc0.w);
    outp[6*S]  = fmaxf(mlp[6*S],  acc1.x);
    outp[7*S]  = fmaxf(mlp[7*S],  acc1.y);
    outp[8*S]  = fmaxf(mlp[8*S],  acc1.z);
    outp[9*S]  = fmaxf(mlp[9*S],  acc1.w);
    outp[10*S] = fmaxf(mlp[10*S], acc2.x);
    outp[11*S] = fmaxf(mlp[11*S], acc2.y);
    outp[12*S] = fmaxf(mlp[12*S], acc2.z);
    outp[13*S] = fmaxf(mlp[13*S], acc2.w);
    outp[14*S] = fmaxf(mlp[14*S], acc3.x);
    outp[15*S] = fmaxf(mlp[15*S], acc3.y);
    outp[16*S] = fmaxf(mlp[16*S], acc3.z);
    outp[17*S] = fmaxf(mlp[17*S], acc3.w);
    outp[18*S] = fmaxf(mlp[18*S], acc4.x);
    outp[19*S] = fmaxf(mlp[19*S], acc4.y);
}

// ---------- window (latency-bound, first) + scratch re-zero for next replay ----------
__global__ void __launch_bounds__(256) window_zero_kernel(const float* __restrict__ maps_last,
                                                          float* __restrict__ dout) {
    if (blockIdx.x < WINDOW_BLOCKS) {
        window_body(blockIdx.x*256 + threadIdx.x, maps_last, dout);
        return;
    }
    int t = (blockIdx.x - WINDOW_BLOCKS)*256 + threadIdx.x;
    float4 z = make_float4(0.f,0.f,0.f,0.f);
    const int n0 = NB*G0_PER_B/4;       // 800000
    const int n1 = NB*GS_PER_B*16/4;    // 1920000
    if (t < n0) ((float4*)g_g0a)[t] = z;
    if (t < n0) ((float4*)g_g0b)[t] = z;
    if (t < n1) ((float4*)g_gs)[t] = z;
}

extern "C" void kernel_launch(void* const* d_in, const int* in_sizes, int n_in,
                              void* d_out, int out_size) {
    const float* obs        = (const float*)d_in[0];
    const float* pose_obs   = (const float*)d_in[1];
    const float* maps_last  = (const float*)d_in[2];
    const float* poses_last = (const float*)d_in[3];
    const float* sh         = (const float*)d_in[4];
    float* out = (float*)d_out;

    pose_kernel<<<1, 32>>>(pose_obs, poses_last, out);
    splat_stream_kernel<<<FAT_BLOCKS, 256>>>(obs, sh, maps_last, out);
    proj_kernel<<<(NB*NCELL*8 + 255)/256, 256>>>(out);
    window_zero_kernel<<<WZ_BLOCKS, 256>>>(maps_last, out);
}

// round 16
// speedup vs baseline: 1.1582x; 1.0253x over previous
#include <cuda_runtime.h>
#include <math.h>

#define NB 4
#define FH 480
#define FW 640
#define NPIX (FH*FW)
#define NSEM 16
#define C_OBS 20
#define VR 100
#define HZ 80
#define MC 480
#define NCELL (VR*VR)          // 10000
#define G0_PER_B (NCELL*HZ)    // 800000
#define AG_Z0 13
#define AG_NZ 12
#define GS_PER_B (NCELL*AG_NZ) // 120000
#define WIN 160

#define SPLAT_BLOCKS (NB*NPIX/256)                 // 4800
#define STREAM_N4    ((size_t)NB*C_OBS*MC*MC/4)    // 4,608,000 float4
#define STREAM_BLOCKS ((int)(STREAM_N4/256))       // 18000
#define FAT_BLOCKS   (SPLAT_BLOCKS + STREAM_BLOCKS)

#define WINDOW_BLOCKS (NB*WIN*WIN*2/256)           // 800
#define ZEROF_BLOCKS ((NB*GS_PER_B*16/4 + 255)/256) // 7500
#define WZ_BLOCKS    (WINDOW_BLOCKS + ZEROF_BLOCKS)

// Output layout: fp_map_pred (NB*NCELL) | map_pred (NB*20*480*480) | poses (12) | poses (12)
#define OUT_MAP_OFF ((size_t)NB*NCELL)
#define OUT_POSE_OFF (OUT_MAP_OFF + (size_t)NB*C_OBS*MC*MC)

// ---------- scratch (zero at module load; window_zero re-zeros for next replay) ----------
__device__ __align__(16) float g_g0a[NB*G0_PER_B];   // ch-0, even-parity pairs; slot z = voxel z
__device__ __align__(16) float g_g0b[NB*G0_PER_B];   // ch-0, odd-parity pairs;  slot z = voxel z+1
__device__ __align__(16) float g_gs[NB*GS_PER_B*16]; // sem voxels [b][(x*100+y)*12+(z-13)][16]
__device__ __align__(16) float g_pall[NB*NCELL*20];  // interleaved proj: [b][y*100+x][20]
__device__ float g_params[NB*8];
__device__ float g_fcal;

// ---------- pose update + sampling params + focal constant (1 tiny block) ----------
__global__ void pose_kernel(const float* __restrict__ pose_obs,
                            const float* __restrict__ poses_last,
                            float* __restrict__ dout) {
    if (threadIdx.x == 0) {
        g_fcal = (float)(320.0 / tan(39.5 * 3.14159265358979323846 / 180.0));
    }
    int b = threadIdx.x;
    if (b >= NB) return;
    const float DEGf = (float)57.29577951308232;
    float pl0 = poses_last[b*3+0], pl1 = poses_last[b*3+1], pl2 = poses_last[b*3+2];
    float po0 = pose_obs[b*3+0],  po1 = pose_obs[b*3+1],  po2 = pose_obs[b*3+2];
    float t0 = pl2 / DEGf;
    float s0 = sinf(t0), c0 = cosf(t0);
    float y_new = pl1 + po0*s0 + po1*c0;
    float x_new = pl0 + po0*c0 - po1*s0;
    float t_new = pl2 + po2*DEGf;
    t_new = fmodf(t_new - 180.0f, 360.0f) + 180.0f;
    t_new = fmodf(t_new + 180.0f, 360.0f) - 180.0f;

    dout[OUT_POSE_OFF      + b*3+0] = x_new;
    dout[OUT_POSE_OFF      + b*3+1] = y_new;
    dout[OUT_POSE_OFF      + b*3+2] = t_new;
    dout[OUT_POSE_OFF + 12 + b*3+0] = x_new;
    dout[OUT_POSE_OFF + 12 + b*3+1] = y_new;
    dout[OUT_POSE_OFF + 12 + b*3+2] = t_new;

    float stx = -(x_new*100.0f/5.0f - 240.0f)/240.0f;
    float sty = -(y_new*100.0f/5.0f - 240.0f)/240.0f;
    float stt = (90.0f - t_new) * (float)0.017453292519943295;
    float ct = cosf(stt), st = sinf(stt);
    float dx = stx * 239.5f;
    float dy = sty * 239.5f;
    g_params[b*8+0] = ct;
    g_params[b*8+1] = st;
    g_params[b*8+2] = dx;
    g_params[b*8+3] = dy;

    float u0 = 189.0f/239.5f - 1.0f, u1 = 290.0f/239.5f - 1.0f;
    float v0 = 239.0f/239.5f - 1.0f, v1 = 340.0f/239.5f - 1.0f;
    float gxmin = 1e9f, gxmax = -1e9f, gymin = 1e9f, gymax = -1e9f;
    #pragma unroll
    for (int k = 0; k < 4; k++) {
        float u = (k & 1) ? u1 : u0;
        float v = (k & 2) ? v1 : v0;
        float gx = ct*u + st*v;
        float gy = -st*u + ct*v;
        gxmin = fminf(gxmin, gx); gxmax = fmaxf(gxmax, gx);
        gymin = fminf(gymin, gy); gymax = fmaxf(gymax, gy);
    }
    float txmin = (gxmin + 1.0f)*239.5f, txmax = (gxmax + 1.0f)*239.5f;
    float tymin = (gymin + 1.0f)*239.5f, tymax = (gymax + 1.0f)*239.5f;
    g_params[b*8+4] = floorf(tymin - dy - 3.0f);
    g_params[b*8+5] = ceilf (tymax - dy + 3.0f);
    g_params[b*8+6] = floorf(txmin - dx - 3.0f);
    g_params[b*8+7] = ceilf (txmax - dx + 3.0f);
}

// ---------- splat body (read-once inputs via __ldcs to protect L2 scratch) ----------
__device__ __forceinline__ void splat_body(int t, const float* __restrict__ obs,
                                           const float* __restrict__ sh) {
    int b   = t / NPIX;
    int pix = t - b*NPIX;
    int i   = pix / FW;
    int j   = pix - i*FW;

    const float* obs_b = obs + (size_t)b*C_OBS*NPIX;
    float depth = __ldcs(&obs_b[3*NPIX + pix]);
    float4 s4   = __ldcs(&((const float4*)sh)[(size_t)b*NPIX + pix]);

    float fc = g_fcal;
    float X = ((float)j - 319.5f) * depth / fc;
    float Z = (239.5f - (float)i) * depth / fc;

    float xn = ((X + 250.0f)/5.0f - 50.0f)/100.0f*2.0f;
    float yn = (depth/5.0f - 50.0f)/100.0f*2.0f;
    float zn = ((Z + 88.0f)/5.0f - 32.0f)/80.0f*2.0f;
    xn = fminf(fmaxf(xn, -1.0f), 1.0f);
    yn = fminf(fmaxf(yn, -1.0f), 1.0f);
    zn = fminf(fmaxf(zn, -1.0f), 1.0f);

    float posx = xn*50.0f + 50.0f;
    float posy = yn*50.0f + 50.0f;
    float posz = zn*40.0f + 40.0f;

    float fx = floorf(posx), fy = floorf(posy), fz = floorf(posz);
    float wx[2], wy[2], wz[2];
    int   px_[2], py_[2], pz_[2];
    #pragma unroll
    for (int k = 0; k < 2; k++) {
        float p;
        p = fx + (float)k; { bool s = (p > 0.0f && p < 100.0f); wx[k] = s ? (1.0f - fabsf(posx - p)) : 0.0f; px_[k] = (int)p; }
        p = fy + (float)k; { bool s = (p > 0.0f && p < 100.0f); wy[k] = s ? (1.0f - fabsf(posy - p)) : 0.0f; py_[k] = (int)p; }
        p = fz + (float)k; { bool s = (p > 0.0f && p <  80.0f); wz[k] = s ? (1.0f - fabsf(posz - p)) : 0.0f; pz_[k] = (int)p; }
    }
    if ((wx[0]==0.0f && wx[1]==0.0f) || (wy[0]==0.0f && wy[1]==0.0f) || (wz[0]==0.0f && wz[1]==0.0f))
        return;

    float sfac = 1.0f + (s4.x + s4.y + s4.z + s4.w) * 0.25f;

    int pz0 = pz_[0], pz1 = pz_[1];
    float wz0 = sfac*wz[0], wz1 = sfac*wz[1];
    bool band0 = (wz[0] != 0.0f) && (pz0 >= AG_Z0) && (pz0 < AG_Z0 + AG_NZ);
    bool band1 = (wz[1] != 0.0f) && (pz1 >= AG_Z0) && (pz1 < AG_Z0 + AG_NZ);

    int odd = pz0 & 1;
    float* g0base = (odd ? g_g0b : g_g0a) + (size_t)b*G0_PER_B + (pz0 - odd);

    float semv[16];
    if (band0 | band1) {
        #pragma unroll
        for (int c = 0; c < 16; c++)
            semv[c] = __ldcs(&obs_b[(4+c)*NPIX + pix]) * sfac;
    }

    float* gsb = g_gs + (size_t)b*GS_PER_B*16;

    #pragma unroll
    for (int kx = 0; kx < 2; kx++) {
        #pragma unroll
        for (int ky = 0; ky < 2; ky++) {
            float wxy = wx[kx]*wy[ky];
            if (wxy == 0.0f) continue;
            int cellxy = px_[kx]*100 + py_[ky];

            atomicAdd((float2*)(g0base + cellxy*80), make_float2(wxy*wz0, wxy*wz1));

            if (band0) {
                float w = wxy*wz[0];
                float* dst = gsb + ((size_t)cellxy*AG_NZ + (pz0 - AG_Z0))*16;
                atomicAdd((float4*)(dst+ 0), make_float4(semv[ 0]*w, semv[ 1]*w, semv[ 2]*w, semv[ 3]*w));
                atomicAdd((float4*)(dst+ 4), make_float4(semv[ 4]*w, semv[ 5]*w, semv[ 6]*w, semv[ 7]*w));
                atomicAdd((float4*)(dst+ 8), make_float4(semv[ 8]*w, semv[ 9]*w, semv[10]*w, semv[11]*w));
                atomicAdd((float4*)(dst+12), make_float4(semv[12]*w, semv[13]*w, semv[14]*w, semv[15]*w));
            }
            if (band1) {
                float w = wxy*wz[1];
                float* dst = gsb + ((size_t)cellxy*AG_NZ + (pz1 - AG_Z0))*16;
                atomicAdd((float4*)(dst+ 0), make_float4(semv[ 0]*w, semv[ 1]*w, semv[ 2]*w, semv[ 3]*w));
                atomicAdd((float4*)(dst+ 4), make_float4(semv[ 4]*w, semv[ 5]*w, semv[ 6]*w, semv[ 7]*w));
                atomicAdd((float4*)(dst+ 8), make_float4(semv[ 8]*w, semv[ 9]*w, semv[10]*w, semv[11]*w));
                atomicAdd((float4*)(dst+12), make_float4(semv[12]*w, semv[13]*w, semv[14]*w, semv[15]*w));
            }
        }
    }
}

// ---------- fat kernel: splat blocks FIRST, stream backfills with L2-bypass hints ----------
__global__ void __launch_bounds__(256) splat_stream_kernel(const float* __restrict__ obs,
                                                           const float* __restrict__ sh,
                                                           const float* __restrict__ maps_last,
                                                           float* __restrict__ dout) {
    if (blockIdx.x < SPLAT_BLOCKS) {
        splat_body(blockIdx.x*256 + threadIdx.x, obs, sh);
    } else {
        size_t t = (size_t)(blockIdx.x - SPLAT_BLOCKS)*256 + threadIdx.x;
        float4 v = __ldcs(&((const float4*)maps_last)[t]);
        v.x = fmaxf(v.x, 0.0f); v.y = fmaxf(v.y, 0.0f);
        v.z = fmaxf(v.z, 0.0f); v.w = fmaxf(v.w, 0.0f);
        __stcs(&((float4*)(dout + OUT_MAP_OFF))[t], v);
    }
}

// ---------- proj : g0-half and sem-half; consumed-once scratch reads via __ldcs ----------
__global__ void __launch_bounds__(256) proj_kernel(float* __restrict__ dout) {
    const int N4 = NB*NCELL*4;
    int t = blockIdx.x*blockDim.x + threadIdx.x;

    if (t < N4) {
        int q = t & 3;
        int cellIdx = t >> 2;
        int b   = cellIdx / NCELL;
        int cxy = cellIdx - b*NCELL;
        int x = cxy / 100, y = cxy - x*100;
        int cell = y*100 + x;

        const float* acell = g_g0a + (size_t)b*G0_PER_B + (size_t)cxy*80;
        const float* bcell = g_g0b + (size_t)b*G0_PER_B + (size_t)cxy*80;
        const float4* a4p = (const float4*)acell + q*5;
        const float4* b4p = (const float4*)bcell + q*5;

        float prev = (q == 0) ? 0.0f : __ldcs(&bcell[q*20 - 1]);

        float a_all = 0.0f, a_ag = 0.0f;
        #pragma unroll
        for (int k = 0; k < 5; k++) {
            float4 a4 = __ldcs(&a4p[k]);
            float4 b4 = __ldcs(&b4p[k]);
            int z = q*20 + k*4;
            float v0 = rintf(a4.x + prev);
            float v1 = rintf(a4.y + b4.x);
            float v2 = rintf(a4.z + b4.y);
            float v3 = rintf(a4.w + b4.z);
            prev = b4.w;
            a_all += v0 + v1 + v2 + v3;
            a_ag += (z+0 >= 13 && z+0 < 25) ? v0 : 0.0f;
            a_ag += (z+1 >= 13 && z+1 < 25) ? v1 : 0.0f;
            a_ag += (z+2 >= 13 && z+2 < 25) ? v2 : 0.0f;
            a_ag += (z+3 >= 13 && z+3 < 25) ? v3 : 0.0f;
        }

        a_all += __shfl_xor_sync(0xFFFFFFFFu, a_all, 1);
        a_all += __shfl_xor_sync(0xFFFFFFFFu, a_all, 2);
        a_ag  += __shfl_xor_sync(0xFFFFFFFFu, a_ag, 1);
        a_ag  += __shfl_xor_sync(0xFFFFFFFFu, a_ag, 2);

        if (q == 0) {
            float pm = fminf(fmaxf(a_ag, 0.0f), 1.0f);
            float pe = fminf(fmaxf(a_all, 0.0f), 1.0f);
            float* rec = g_pall + ((size_t)b*NCELL + cell)*20;
            rec[0] = pm;
            rec[1] = pe;
            dout[(size_t)b*NCELL + cell] = pm;
        }
    } else {
        int u = t - N4;
        if (u >= N4) return;
        int q = u & 3;
        int cellIdx = u >> 2;
        int b   = cellIdx / NCELL;
        int cxy = cellIdx - b*NCELL;
        int x = cxy / 100, y = cxy - x*100;
        int cell = y*100 + x;

        const float4* gsp = (const float4*)(g_gs + ((size_t)b*GS_PER_B + (size_t)cxy*AG_NZ)*16) + q;
        float4 acc = make_float4(0.f,0.f,0.f,0.f);
        #pragma unroll
        for (int zz = 0; zz < AG_NZ; zz++) {
            float4 v = __ldcs(&gsp[zz*4]);
            acc.x += rintf(v.x);
            acc.y += rintf(v.y);
            acc.z += rintf(v.z);
            acc.w += rintf(v.w);
        }

        float* rec = g_pall + ((size_t)b*NCELL + cell)*20;
        rec[2 + q*4 + 0] = fminf(fmaxf(acc.x / 5.0f, 0.0f), 1.0f);
        rec[2 + q*4 + 1] = fminf(fmaxf(acc.y / 5.0f, 0.0f), 1.0f);
        rec[2 + q*4 + 2] = fminf(fmaxf(acc.z / 5.0f, 0.0f), 1.0f);
        rec[2 + q*4 + 3] = fminf(fmaxf(acc.w / 5.0f, 0.0f), 1.0f);
        if (q == 3) {
            rec[18] = 0.0f;
            rec[19] = 0.0f;
        }
    }
}

// ---------- window body : 2 threads/pixel (measured-best) ----------
__device__ __forceinline__ void window_body(int t, const float* __restrict__ maps_last,
                                            float* __restrict__ dout) {
    int half  = t & 1;
    int pixId = t >> 1;
    int b   = pixId / (WIN*WIN);
    int rem = pixId - b*(WIN*WIN);
    int li = rem / WIN, lj = rem - li*WIN;

    float ct = g_params[b*8+0], st = g_params[b*8+1];
    float dx = g_params[b*8+2], dy = g_params[b*8+3];
    int bi0 = (int)g_params[b*8+4], bi1 = (int)g_params[b*8+5];
    int bj0 = (int)g_params[b*8+6], bj1 = (int)g_params[b*8+7];

    int i = bi0 + li;
    int j = bj0 + lj;
    bool valid = (i <= bi1) && (j <= bj1) && (i >= 0) && (i < MC) && (j >= 0) && (j < MC);

    float xs = (float)j + dx, ys = (float)i + dy;
    float x0f = floorf(xs), y0f = floorf(ys);
    float wxb = xs - x0f, wxa = 1.0f - wxb;
    float wyb = ys - y0f, wya = 1.0f - wyb;
    int ix0 = (int)x0f, iy0 = (int)y0f;

    const float4* pall4 = (const float4*)(g_pall + (size_t)b*NCELL*20);

    float4 acc0 = make_float4(0,0,0,0), acc1 = acc0, acc2 = acc0, acc3 = acc0, acc4 = acc0;

    #pragma unroll
    for (int kk = 0; kk < 2; kk++) {
        int k  = half*2 + kk;
        int tx = ix0 + (k & 1);
        int ty = iy0 + (k >> 1);
        bool tvalid = valid && (tx >= 0) && (tx < MC) && (ty >= 0) && (ty < MC);
        float twk = ((k & 1) ? wxb : wxa) * ((k >> 1) ? wyb : wya);

        float gxr = -1.0f + (float)tx * (2.0f/479.0f);
        float gyr = -1.0f + (float)ty * (2.0f/479.0f);
        float xr = ((ct*gxr - st*gyr) + 1.0f) * 239.5f;
        float yr = ((st*gxr + ct*gyr) + 1.0f) * 239.5f;
        float rx0f = floorf(xr), ry0f = floorf(yr);
        float rb = xr - rx0f, ra = 1.0f - rb;
        float rd = yr - ry0f, rc = 1.0f - rd;
        int rx0 = (int)rx0f, ry0 = (int)ry0f;

        #pragma unroll
        for (int s = 0; s < 4; s++) {
            int ix = rx0 + (s & 1);
            int iy = ry0 + (s >> 1);
            bool in = tvalid && (ix >= 190) && (ix < 290) && (iy >= 240) && (iy < 340);
            if (in) {
                float rw = ((s & 1) ? rb : ra) * ((s >> 1) ? rd : rc);
                float w = twk * rw;
                const float4* rp = pall4 + ((iy - 240)*100 + (ix - 190))*5;
                float4 r0 = rp[0], r1 = rp[1], r2 = rp[2], r3 = rp[3], r4 = rp[4];
                acc0.x += w*r0.x; acc0.y += w*r0.y; acc0.z += w*r0.z; acc0.w += w*r0.w;
                acc1.x += w*r1.x; acc1.y += w*r1.y; acc1.z += w*r1.z; acc1.w += w*r1.w;
                acc2.x += w*r2.x; acc2.y += w*r2.y; acc2.z += w*r2.z; acc2.w += w*r2.w;
                acc3.x += w*r3.x; acc3.y += w*r3.y; acc3.z += w*r3.z; acc3.w += w*r3.w;
                acc4.x += w*r4.x; acc4.y += w*r4.y;
            }
        }
    }

    acc0.x += __shfl_xor_sync(0xFFFFFFFFu, acc0.x, 1);
    acc0.y += __shfl_xor_sync(0xFFFFFFFFu, acc0.y, 1);
    acc0.z += __shfl_xor_sync(0xFFFFFFFFu, acc0.z, 1);
    acc0.w += __shfl_xor_sync(0xFFFFFFFFu, acc0.w, 1);
    acc1.x += __shfl_xor_sync(0xFFFFFFFFu, acc1.x, 1);
    acc1.y += __shfl_xor_sync(0xFFFFFFFFu, acc1.y, 1);
    acc1.z += __shfl_xor_sync(0xFFFFFFFFu, acc1.z, 1);
    acc1.w += __shfl_xor_sync(0xFFFFFFFFu, acc1.w, 1);
    acc2.x += __shfl_xor_sync(0xFFFFFFFFu, acc2.x, 1);
    acc2.y += __shfl_xor_sync(0xFFFFFFFFu, acc2.y, 1);
    acc2.z += __shfl_xor_sync(0xFFFFFFFFu, acc2.z, 1);
    acc2.w += __shfl_xor_sync(0xFFFFFFFFu, acc2.w, 1);
    acc3.x += __shfl_xor_sync(0xFFFFFFFFu, acc3.x, 1);
    acc3.y += __shfl_xor_sync(0xFFFFFFFFu, acc3.y, 1);
    acc3.z += __shfl_xor_sync(0xFFFFFFFFu, acc3.z, 1);
    acc3.w += __shfl_xor_sync(0xFFFFFFFFu, acc3.w, 1);
    acc4.x += __shfl_xor_sync(0xFFFFFFFFu, acc4.x, 1);
    acc4.y += __shfl_xor_sync(0xFFFFFFFFu, acc4.y, 1);

    if (half != 0 || !valid) return;

    size_t base = (size_t)b*C_OBS*MC*MC + (size_t)i*MC + j;
    const float* mlp  = maps_last + base;
    float*       outp = dout + OUT_MAP_OFF + base;
    const size_t S = (size_t)MC*MC;

    outp[0]    = fmaxf(mlp[0],    acc0.x);
    outp[S]    = fmaxf(mlp[S],    acc0.y);
    outp[4*S]  = fmaxf(mlp[4*S],  acc0.z);
    outp[5*S]  = fmaxf(mlp[5*S],  acc0.w);
    outp[6*S]  = fmaxf(mlp[6*S],  acc1.x);
    outp[7*S]  = fmaxf(mlp[7*S],  acc1.y);
    outp[8*S]  = fmaxf(mlp[8*S],  acc1.z);
    outp[9*S]  = fmaxf(mlp[9*S],  acc1.w);
    outp[10*S] = fmaxf(mlp[10*S], acc2.x);
    outp[11*S] = fmaxf(mlp[11*S], acc2.y);
    outp[12*S] = fmaxf(mlp[12*S], acc2.z);
    outp[13*S] = fmaxf(mlp[13*S], acc2.w);
    outp[14*S] = fmaxf(mlp[14*S], acc3.x);
    outp[15*S] = fmaxf(mlp[15*S], acc3.y);
    outp[16*S] = fmaxf(mlp[16*S], acc3.z);
    outp[17*S] = fmaxf(mlp[17*S], acc3.w);
    outp[18*S] = fmaxf(mlp[18*S], acc4.x);
    outp[19*S] = fmaxf(mlp[19*S], acc4.y);
}

// ---------- window (latency-bound, first) + scratch re-zero for next replay ----------
__global__ void __launch_bounds__(256) window_zero_kernel(const float* __restrict__ maps_last,
                                                          float* __restrict__ dout) {
    if (blockIdx.x < WINDOW_BLOCKS) {
        window_body(blockIdx.x*256 + threadIdx.x, maps_last, dout);
        return;
    }
    int t = (blockIdx.x - WINDOW_BLOCKS)*256 + threadIdx.x;
    float4 z = make_float4(0.f,0.f,0.f,0.f);
    const int n0 = NB*G0_PER_B/4;       // 800000
    const int n1 = NB*GS_PER_B*16/4;    // 1920000
    if (t < n0) ((float4*)g_g0a)[t] = z;
    if (t < n0) ((float4*)g_g0b)[t] = z;
    if (t < n1) ((float4*)g_gs)[t] = z;
}

extern "C" void kernel_launch(void* const* d_in, const int* in_sizes, int n_in,
                              void* d_out, int out_size) {
    const float* obs        = (const float*)d_in[0];
    const float* pose_obs   = (const float*)d_in[1];
    const float* maps_last  = (const float*)d_in[2];
    const float* poses_last = (const float*)d_in[3];
    const float* sh         = (const float*)d_in[4];
    float* out = (float*)d_out;

    pose_kernel<<<1, 32>>>(pose_obs, poses_last, out);
    splat_stream_kernel<<<FAT_BLOCKS, 256>>>(obs, sh, maps_last, out);
    proj_kernel<<<(NB*NCELL*8 + 255)/256, 256>>>(out);
    window_zero_kernel<<<WZ_BLOCKS, 256>>>(maps_last, out);
}

// round 17
// speedup vs baseline: 1.1625x; 1.0037x over previous
#include <cuda_runtime.h>
#include <math.h>

#define NB 4
#define FH 480
#define FW 640
#define NPIX (FH*FW)
#define NSEM 16
#define C_OBS 20
#define VR 100
#define HZ 80
#define MC 480
#define NCELL (VR*VR)          // 10000
#define G0_PER_B (NCELL*HZ)    // 800000
#define AG_Z0 13
#define AG_NZ 12
#define GS_PER_B (NCELL*AG_NZ) // 120000
#define WIN 160

#define SPLAT_BLOCKS (NB*NPIX/256)                 // 4800
#define STREAM_N4    ((size_t)NB*C_OBS*MC*MC/4)    // 4,608,000 float4
#define STREAM_BLOCKS ((int)(STREAM_N4/256))       // 18000
#define FAT_BLOCKS   (SPLAT_BLOCKS + STREAM_BLOCKS)

#define WINDOW_BLOCKS (NB*WIN*WIN*2/256)           // 800
#define ZEROF_BLOCKS ((NB*GS_PER_B*16/4 + 255)/256) // 7500
#define WZ_BLOCKS    (WINDOW_BLOCKS + ZEROF_BLOCKS)

// Output layout: fp_map_pred (NB*NCELL) | map_pred (NB*20*480*480) | poses (12) | poses (12)
#define OUT_MAP_OFF ((size_t)NB*NCELL)
#define OUT_POSE_OFF (OUT_MAP_OFF + (size_t)NB*C_OBS*MC*MC)

// ---------- scratch (zero at module load; window_zero re-zeros for next replay) ----------
__device__ __align__(16) float g_g0a[NB*G0_PER_B];   // ch-0, even-parity pairs; slot z = voxel z
__device__ __align__(16) float g_g0b[NB*G0_PER_B];   // ch-0, odd-parity pairs;  slot z = voxel z+1
__device__ __align__(16) float g_gs[NB*GS_PER_B*16]; // sem voxels [b][(x*100+y)*12+(z-13)][16]
__device__ __align__(16) float g_pall[NB*NCELL*20];  // interleaved proj: [b][y*100+x][20]
__device__ float g_params[NB*8];
__device__ float g_fcal;

#if defined(__CUDA_ARCH__) && (__CUDA_ARCH__ >= 900)
#define GRID_DEP_SYNC() cudaGridDependencySynchronize()
#else
#define GRID_DEP_SYNC()
#endif

// ---------- pose update + sampling params + focal constant (1 tiny block) ----------
__global__ void pose_kernel(const float* __restrict__ pose_obs,
                            const float* __restrict__ poses_last,
                            float* __restrict__ dout) {
    if (threadIdx.x == 0) {
        g_fcal = (float)(320.0 / tan(39.5 * 3.14159265358979323846 / 180.0));
    }
    int b = threadIdx.x;
    if (b >= NB) return;
    const float DEGf = (float)57.29577951308232;
    float pl0 = poses_last[b*3+0], pl1 = poses_last[b*3+1], pl2 = poses_last[b*3+2];
    float po0 = pose_obs[b*3+0],  po1 = pose_obs[b*3+1],  po2 = pose_obs[b*3+2];
    float t0 = pl2 / DEGf;
    float s0 = sinf(t0), c0 = cosf(t0);
    float y_new = pl1 + po0*s0 + po1*c0;
    float x_new = pl0 + po0*c0 - po1*s0;
    float t_new = pl2 + po2*DEGf;
    t_new = fmodf(t_new - 180.0f, 360.0f) + 180.0f;
    t_new = fmodf(t_new + 180.0f, 360.0f) - 180.0f;

    dout[OUT_POSE_OFF      + b*3+0] = x_new;
    dout[OUT_POSE_OFF      + b*3+1] = y_new;
    dout[OUT_POSE_OFF      + b*3+2] = t_new;
    dout[OUT_POSE_OFF + 12 + b*3+0] = x_new;
    dout[OUT_POSE_OFF + 12 + b*3+1] = y_new;
    dout[OUT_POSE_OFF + 12 + b*3+2] = t_new;

    float stx = -(x_new*100.0f/5.0f - 240.0f)/240.0f;
    float sty = -(y_new*100.0f/5.0f - 240.0f)/240.0f;
    float stt = (90.0f - t_new) * (float)0.017453292519943295;
    float ct = cosf(stt), st = sinf(stt);
    float dx = stx * 239.5f;
    float dy = sty * 239.5f;
    g_params[b*8+0] = ct;
    g_params[b*8+1] = st;
    g_params[b*8+2] = dx;
    g_params[b*8+3] = dy;

    float u0 = 189.0f/239.5f - 1.0f, u1 = 290.0f/239.5f - 1.0f;
    float v0 = 239.0f/239.5f - 1.0f, v1 = 340.0f/239.5f - 1.0f;
    float gxmin = 1e9f, gxmax = -1e9f, gymin = 1e9f, gymax = -1e9f;
    #pragma unroll
    for (int k = 0; k < 4; k++) {
        float u = (k & 1) ? u1 : u0;
        float v = (k & 2) ? v1 : v0;
        float gx = ct*u + st*v;
        float gy = -st*u + ct*v;
        gxmin = fminf(gxmin, gx); gxmax = fmaxf(gxmax, gx);
        gymin = fminf(gymin, gy); gymax = fmaxf(gymax, gy);
    }
    float txmin = (gxmin + 1.0f)*239.5f, txmax = (gxmax + 1.0f)*239.5f;
    float tymin = (gymin + 1.0f)*239.5f, tymax = (gymax + 1.0f)*239.5f;
    g_params[b*8+4] = floorf(tymin - dy - 3.0f);
    g_params[b*8+5] = ceilf (tymax - dy + 3.0f);
    g_params[b*8+6] = floorf(txmin - dx - 3.0f);
    g_params[b*8+7] = ceilf (txmax - dx + 3.0f);
}

// ---------- splat body (read-once inputs via __ldcs) ----------
__device__ __forceinline__ void splat_body(int t, const float* __restrict__ obs,
                                           const float* __restrict__ sh) {
    int b   = t / NPIX;
    int pix = t - b*NPIX;
    int i   = pix / FW;
    int j   = pix - i*FW;

    const float* obs_b = obs + (size_t)b*C_OBS*NPIX;
    float depth = __ldcs(&obs_b[3*NPIX + pix]);
    float4 s4   = __ldcs(&((const float4*)sh)[(size_t)b*NPIX + pix]);

    float fc = g_fcal;
    float X = ((float)j - 319.5f) * depth / fc;
    float Z = (239.5f - (float)i) * depth / fc;

    float xn = ((X + 250.0f)/5.0f - 50.0f)/100.0f*2.0f;
    float yn = (depth/5.0f - 50.0f)/100.0f*2.0f;
    float zn = ((Z + 88.0f)/5.0f - 32.0f)/80.0f*2.0f;
    xn = fminf(fmaxf(xn, -1.0f), 1.0f);
    yn = fminf(fmaxf(yn, -1.0f), 1.0f);
    zn = fminf(fmaxf(zn, -1.0f), 1.0f);

    float posx = xn*50.0f + 50.0f;
    float posy = yn*50.0f + 50.0f;
    float posz = zn*40.0f + 40.0f;

    float fx = floorf(posx), fy = floorf(posy), fz = floorf(posz);
    float wx[2], wy[2], wz[2];
    int   px_[2], py_[2], pz_[2];
    #pragma unroll
    for (int k = 0; k < 2; k++) {
        float p;
        p = fx + (float)k; { bool s = (p > 0.0f && p < 100.0f); wx[k] = s ? (1.0f - fabsf(posx - p)) : 0.0f; px_[k] = (int)p; }
        p = fy + (float)k; { bool s = (p > 0.0f && p < 100.0f); wy[k] = s ? (1.0f - fabsf(posy - p)) : 0.0f; py_[k] = (int)p; }
        p = fz + (float)k; { bool s = (p > 0.0f && p <  80.0f); wz[k] = s ? (1.0f - fabsf(posz - p)) : 0.0f; pz_[k] = (int)p; }
    }
    if ((wx[0]==0.0f && wx[1]==0.0f) || (wy[0]==0.0f && wy[1]==0.0f) || (wz[0]==0.0f && wz[1]==0.0f))
        return;

    float sfac = 1.0f + (s4.x + s4.y + s4.z + s4.w) * 0.25f;

    int pz0 = pz_[0], pz1 = pz_[1];
    float wz0 = sfac*wz[0], wz1 = sfac*wz[1];
    bool band0 = (wz[0] != 0.0f) && (pz0 >= AG_Z0) && (pz0 < AG_Z0 + AG_NZ);
    bool band1 = (wz[1] != 0.0f) && (pz1 >= AG_Z0) && (pz1 < AG_Z0 + AG_NZ);

    int odd = pz0 & 1;
    float* g0base = (odd ? g_g0b : g_g0a) + (size_t)b*G0_PER_B + (pz0 - odd);

    float semv[16];
    if (band0 | band1) {
        #pragma unroll
        for (int c = 0; c < 16; c++)
            semv[c] = __ldcs(&obs_b[(4+c)*NPIX + pix]) * sfac;
    }

    float* gsb = g_gs + (size_t)b*GS_PER_B*16;

    #pragma unroll
    for (int kx = 0; kx < 2; kx++) {
        #pragma unroll
        for (int ky = 0; ky < 2; ky++) {
            float wxy = wx[kx]*wy[ky];
            if (wxy == 0.0f) continue;
            int cellxy = px_[kx]*100 + py_[ky];

            atomicAdd((float2*)(g0base + cellxy*80), make_float2(wxy*wz0, wxy*wz1));

            if (band0) {
                float w = wxy*wz[0];
                float* dst = gsb + ((size_t)cellxy*AG_NZ + (pz0 - AG_Z0))*16;
                atomicAdd((float4*)(dst+ 0), make_float4(semv[ 0]*w, semv[ 1]*w, semv[ 2]*w, semv[ 3]*w));
                atomicAdd((float4*)(dst+ 4), make_float4(semv[ 4]*w, semv[ 5]*w, semv[ 6]*w, semv[ 7]*w));
                atomicAdd((float4*)(dst+ 8), make_float4(semv[ 8]*w, semv[ 9]*w, semv[10]*w, semv[11]*w));
                atomicAdd((float4*)(dst+12), make_float4(semv[12]*w, semv[13]*w, semv[14]*w, semv[15]*w));
            }
            if (band1) {
                float w = wxy*wz[1];
                float* dst = gsb + ((size_t)cellxy*AG_NZ + (pz1 - AG_Z0))*16;
                atomicAdd((float4*)(dst+ 0), make_float4(semv[ 0]*w, semv[ 1]*w, semv[ 2]*w, semv[ 3]*w));
                atomicAdd((float4*)(dst+ 4), make_float4(semv[ 4]*w, semv[ 5]*w, semv[ 6]*w, semv[ 7]*w));
                atomicAdd((float4*)(dst+ 8), make_float4(semv[ 8]*w, semv[ 9]*w, semv[10]*w, semv[11]*w));
                atomicAdd((float4*)(dst+12), make_float4(semv[12]*w, semv[13]*w, semv[14]*w, semv[15]*w));
            }
        }
    }
}

// ---------- fat kernel: splat blocks FIRST, stream backfills with L2-bypass hints ----------
__global__ void __launch_bounds__(256) splat_stream_kernel(const float* __restrict__ obs,
                                                           const float* __restrict__ sh,
                                                           const float* __restrict__ maps_last,
                                                           float* __restrict__ dout) {
    if (blockIdx.x < SPLAT_BLOCKS) {
        GRID_DEP_SYNC();   // wait for pose_kernel's g_fcal
        splat_body(blockIdx.x*256 + threadIdx.x, obs, sh);
    } else {
        size_t t = (size_t)(blockIdx.x - SPLAT_BLOCKS)*256 + threadIdx.x;
        float4 v = __ldcs(&((const float4*)maps_last)[t]);
        v.x = fmaxf(v.x, 0.0f); v.y = fmaxf(v.y, 0.0f);
        v.z = fmaxf(v.z, 0.0f); v.w = fmaxf(v.w, 0.0f);
        __stcs(&((float4*)(dout + OUT_MAP_OFF))[t], v);
    }
}

// ---------- proj : g0-half and sem-half; consumed-once scratch reads via __ldcs ----------
__global__ void __launch_bounds__(256) proj_kernel(float* __restrict__ dout) {
    GRID_DEP_SYNC();   // wait for splat_stream's scratch writes
    const int N4 = NB*NCELL*4;
    int t = blockIdx.x*blockDim.x + threadIdx.x;

    if (t < N4) {
        int q = t & 3;
        int cellIdx = t >> 2;
        int b   = cellIdx / NCELL;
        int cxy = cellIdx - b*NCELL;
        int x = cxy / 100, y = cxy - x*100;
        int cell = y*100 + x;

        const float* acell = g_g0a + (size_t)b*G0_PER_B + (size_t)cxy*80;
        const float* bcell = g_g0b + (size_t)b*G0_PER_B + (size_t)cxy*80;
        const float4* a4p = (const float4*)acell + q*5;
        const float4* b4p = (const float4*)bcell + q*5;

        float prev = (q == 0) ? 0.0f : __ldcs(&bcell[q*20 - 1]);

        float a_all = 0.0f, a_ag = 0.0f;
        #pragma unroll
        for (int k = 0; k < 5; k++) {
            float4 a4 = __ldcs(&a4p[k]);
            float4 b4 = __ldcs(&b4p[k]);
            int z = q*20 + k*4;
            float v0 = rintf(a4.x + prev);
            float v1 = rintf(a4.y + b4.x);
            float v2 = rintf(a4.z + b4.y);
            float v3 = rintf(a4.w + b4.z);
            prev = b4.w;
            a_all += v0 + v1 + v2 + v3;
            a_ag += (z+0 >= 13 && z+0 < 25) ? v0 : 0.0f;
            a_ag += (z+1 >= 13 && z+1 < 25) ? v1 : 0.0f;
            a_ag += (z+2 >= 13 && z+2 < 25) ? v2 : 0.0f;
            a_ag += (z+3 >= 13 && z+3 < 25) ? v3 : 0.0f;
        }

        a_all += __shfl_xor_sync(0xFFFFFFFFu, a_all, 1);
        a_all += __shfl_xor_sync(0xFFFFFFFFu, a_all, 2);
        a_ag  += __shfl_xor_sync(0xFFFFFFFFu, a_ag, 1);
        a_ag  += __shfl_xor_sync(0xFFFFFFFFu, a_ag, 2);

        if (q == 0) {
            float pm = fminf(fmaxf(a_ag, 0.0f), 1.0f);
            float pe = fminf(fmaxf(a_all, 0.0f), 1.0f);
            float* rec = g_pall + ((size_t)b*NCELL + cell)*20;
            rec[0] = pm;
            rec[1] = pe;
            dout[(size_t)b*NCELL + cell] = pm;
        }
    } else {
        int u = t - N4;
        if (u >= N4) return;
        int q = u & 3;
        int cellIdx = u >> 2;
        int b   = cellIdx / NCELL;
        int cxy = cellIdx - b*NCELL;
        int x = cxy / 100, y = cxy - x*100;
        int cell = y*100 + x;

        const float4* gsp = (const float4*)(g_gs + ((size_t)b*GS_PER_B + (size_t)cxy*AG_NZ)*16) + q;
        float4 acc = make_float4(0.f,0.f,0.f,0.f);
        #pragma unroll
        for (int zz = 0; zz < AG_NZ; zz++) {
            float4 v = __ldcs(&gsp[zz*4]);
            acc.x += rintf(v.x);
            acc.y += rintf(v.y);
            acc.z += rintf(v.z);
            acc.w += rintf(v.w);
        }

        float* rec = g_pall + ((size_t)b*NCELL + cell)*20;
        rec[2 + q*4 + 0] = fminf(fmaxf(acc.x / 5.0f, 0.0f), 1.0f);
        rec[2 + q*4 + 1] = fminf(fmaxf(acc.y / 5.0f, 0.0f), 1.0f);
        rec[2 + q*4 + 2] = fminf(fmaxf(acc.z / 5.0f, 0.0f), 1.0f);
        rec[2 + q*4 + 3] = fminf(fmaxf(acc.w / 5.0f, 0.0f), 1.0f);
        if (q == 3) {
            rec[18] = 0.0f;
            rec[19] = 0.0f;
        }
    }
}

// ---------- window body : 2 threads/pixel (measured-best) ----------
__device__ __forceinline__ void window_body(int t, const float* __restrict__ maps_last,
                                            float* __restrict__ dout) {
    int half  = t & 1;
    int pixId = t >> 1;
    int b   = pixId / (WIN*WIN);
    int rem = pixId - b*(WIN*WIN);
    int li = rem / WIN, lj = rem - li*WIN;

    float ct = g_params[b*8+0], st = g_params[b*8+1];
    float dx = g_params[b*8+2], dy = g_params[b*8+3];
    int bi0 = (int)g_params[b*8+4], bi1 = (int)g_params[b*8+5];
    int bj0 = (int)g_params[b*8+6], bj1 = (int)g_params[b*8+7];

    int i = bi0 + li;
    int j = bj0 + lj;
    bool valid = (i <= bi1) && (j <= bj1) && (i >= 0) && (i < MC) && (j >= 0) && (j < MC);

    float xs = (float)j + dx, ys = (float)i + dy;
    float x0f = floorf(xs), y0f = floorf(ys);
    float wxb = xs - x0f, wxa = 1.0f - wxb;
    float wyb = ys - y0f, wya = 1.0f - wyb;
    int ix0 = (int)x0f, iy0 = (int)y0f;

    const float4* pall4 = (const float4*)(g_pall + (size_t)b*NCELL*20);

    float4 acc0 = make_float4(0,0,0,0), acc1 = acc0, acc2 = acc0, acc3 = acc0, acc4 = acc0;

    #pragma unroll
    for (int kk = 0; kk < 2; kk++) {
        int k  = half*2 + kk;
        int tx = ix0 + (k & 1);
        int ty = iy0 + (k >> 1);
        bool tvalid = valid && (tx >= 0) && (tx < MC) && (ty >= 0) && (ty < MC);
        float twk = ((k & 1) ? wxb : wxa) * ((k >> 1) ? wyb : wya);

        float gxr = -1.0f + (float)tx * (2.0f/479.0f);
        float gyr = -1.0f + (float)ty * (2.0f/479.0f);
        float xr = ((ct*gxr - st*gyr) + 1.0f) * 239.5f;
        float yr = ((st*gxr + ct*gyr) + 1.0f) * 239.5f;
        float rx0f = floorf(xr), ry0f = floorf(yr);
        float rb = xr - rx0f, ra = 1.0f - rb;
        float rd = yr - ry0f, rc = 1.0f - rd;
        int rx0 = (int)rx0f, ry0 = (int)ry0f;

        #pragma unroll
        for (int s = 0; s < 4; s++) {
            int ix = rx0 + (s & 1);
            int iy = ry0 + (s >> 1);
            bool in = tvalid && (ix >= 190) && (ix < 290) && (iy >= 240) && (iy < 340);
            if (in) {
                float rw = ((s & 1) ? rb : ra) * ((s >> 1) ? rd : rc);
                float w = twk * rw;
                const float4* rp = pall4 + ((iy - 240)*100 + (ix - 190))*5;
                float4 r0 = rp[0], r1 = rp[1], r2 = rp[2], r3 = rp[3], r4 = rp[4];
                acc0.x += w*r0.x; acc0.y += w*r0.y; acc0.z += w*r0.z; acc0.w += w*r0.w;
                acc1.x += w*r1.x; acc1.y += w*r1.y; acc1.z += w*r1.z; acc1.w += w*r1.w;
                acc2.x += w*r2.x; acc2.y += w*r2.y; acc2.z += w*r2.z; acc2.w += w*r2.w;
                acc3.x += w*r3.x; acc3.y += w*r3.y; acc3.z += w*r3.z; acc3.w += w*r3.w;
                acc4.x += w*r4.x; acc4.y += w*r4.y;
            }
        }
    }

    acc0.x += __shfl_xor_sync(0xFFFFFFFFu, acc0.x, 1);
    acc0.y += __shfl_xor_sync(0xFFFFFFFFu, acc0.y, 1);
    acc0.z += __shfl_xor_sync(0xFFFFFFFFu, acc0.z, 1);
    acc0.w += __shfl_xor_sync(0xFFFFFFFFu, acc0.w, 1);
    acc1.x += __shfl_xor_sync(0xFFFFFFFFu, acc1.x, 1);
    acc1.y += __shfl_xor_sync(0xFFFFFFFFu, acc1.y, 1);
    acc1.z += __shfl_xor_sync(0xFFFFFFFFu, acc1.z, 1);
    acc1.w += __shfl_xor_sync(0xFFFFFFFFu, acc1.w, 1);
    acc2.x += __shfl_xor_sync(0xFFFFFFFFu, acc2.x, 1);
    acc2.y += __shfl_xor_sync(0xFFFFFFFFu, acc2.y, 1);
    acc2.z += __shfl_xor_sync(0xFFFFFFFFu, acc2.z, 1);
    acc2.w += __shfl_xor_sync(0xFFFFFFFFu, acc2.w, 1);
    acc3.x += __shfl_xor_sync(0xFFFFFFFFu, acc3.x, 1);
    acc3.y += __shfl_xor_sync(0xFFFFFFFFu, acc3.y, 1);
    acc3.z += __shfl_xor_sync(0xFFFFFFFFu, acc3.z, 1);
    acc3.w += __shfl_xor_sync(0xFFFFFFFFu, acc3.w, 1);
    acc4.x += __shfl_xor_sync(0xFFFFFFFFu, acc4.x, 1);
    acc4.y += __shfl_xor_sync(0xFFFFFFFFu, acc4.y, 1);

    if (half != 0 || !valid) return;

    size_t base = (size_t)b*C_OBS*MC*MC + (size_t)i*MC + j;
    const float* mlp  = maps_last + base;
    float*       outp = dout + OUT_MAP_OFF + base;
    const size_t S = (size_t)MC*MC;

    outp[0]    = fmaxf(mlp[0],    acc0.x);
    outp[S]    = fmaxf(mlp[S],    acc0.y);
    outp[4*S]  = fmaxf(mlp[4*S],  acc0.z);
    outp[5*S]  = fmaxf(mlp[5*S],  acc0.w);
    outp[6*S]  = fmaxf(mlp[6*S],  acc1.x);
    outp[7*S]  = fmaxf(mlp[7*S],  acc1.y);
    outp[8*S]  = fmaxf(mlp[8*S],  acc1.z);
    outp[9*S]  = fmaxf(mlp[9*S],  acc1.w);
    outp[10*S] = fmaxf(mlp[10*S], acc2.x);
    outp[11*S] = fmaxf(mlp[11*S], acc2.y);
    outp[12*S] = fmaxf(mlp[12*S], acc2.z);
    outp[13*S] = fmaxf(mlp[13*S], acc2.w);
    outp[14*S] = fmaxf(mlp[14*S], acc3.x);
    outp[15*S] = fmaxf(mlp[15*S], acc3.y);
    outp[16*S] = fmaxf(mlp[16*S], acc3.z);
    outp[17*S] = fmaxf(mlp[17*S], acc3.w);
    outp[18*S] = fmaxf(mlp[18*S], acc4.x);
    outp[19*S] = fmaxf(mlp[19*S], acc4.y);
}

// ---------- window (latency-bound, first) + scratch re-zero for next replay ----------
__global__ void __launch_bounds__(256) window_zero_kernel(const float* __restrict__ maps_last,
                                                          float* __restrict__ dout) {
    GRID_DEP_SYNC();   // wait for proj_kernel's g_pall writes / scratch reads
    if (blockIdx.x < WINDOW_BLOCKS) {
        window_body(blockIdx.x*256 + threadIdx.x, maps_last, dout);
        return;
    }
    int t = (blockIdx.x - WINDOW_BLOCKS)*256 + threadIdx.x;
    float4 z = make_float4(0.f,0.f,0.f,0.f);
    const int n0 = NB*G0_PER_B/4;       // 800000
    const int n1 = NB*GS_PER_B*16/4;    // 1920000
    if (t < n0) ((float4*)g_g0a)[t] = z;
    if (t < n0) ((float4*)g_g0b)[t] = z;
    if (t < n1) ((float4*)g_gs)[t] = z;
}

// ---------- PDL launch helper ----------
template <typename... Args>
static inline void launch_pdl(void (*kernel)(Args...), int grid, Args... args) {
    cudaLaunchConfig_t cfg = {};
    cudaLaunchAttribute attr[1];
    attr[0].id = cudaLaunchAttributeProgrammaticStreamSerialization;
    attr[0].val.programmaticStreamSerializationAllowed = 1;
    cfg.gridDim = dim3(grid);
    cfg.blockDim = dim3(256);
    cfg.dynamicSmemBytes = 0;
    cfg.stream = 0;
    cfg.attrs = attr;
    cfg.numAttrs = 1;
    cudaLaunchKernelEx(&cfg, kernel, args...);
}

extern "C" void kernel_launch(void* const* d_in, const int* in_sizes, int n_in,
                              void* d_out, int out_size) {
    const float* obs        = (const float*)d_in[0];
    const float* pose_obs   = (const float*)d_in[1];
    const float* maps_last  = (const float*)d_in[2];
    const float* poses_last = (const float*)d_in[3];
    const float* sh         = (const float*)d_in[4];
    float* out = (float*)d_out;

    pose_kernel<<<1, 32>>>(pose_obs, poses_last, out);
    launch_pdl(splat_stream_kernel, FAT_BLOCKS, obs, sh, maps_last, (float*)out);
    launch_pdl(proj_kernel, (NB*NCELL*8 + 255)/256, (float*)out);
    launch_pdl(window_zero_kernel, WZ_BLOCKS, maps_last, (float*)out);
}